// round 4
// baseline (speedup 1.0000x reference)
#include <cuda_runtime.h>
#include <cstdint>
#include <math.h>

// ---------------- problem constants ----------------
#define NB    8
#define NTOK  4096
#define NCH   1024
#define NH    16
#define NL    64
#define ND    64
#define NCHK  32
#define MSEL  (NB*NCHK*64)        // 16384 selected rows
#define MFULL (NB*NTOK)           // 32768

// ---------------- scratch (device globals) -------------------------------
__device__ float g_Kh[(size_t)MSEL*NCH];
__device__ float g_Vh[(size_t)MSEL*NCH];
__device__ float g_G [(size_t)MFULL*NCH];
__device__ float g_Wt[(size_t)MFULL*NCH];
__device__ float g_xr[(size_t)MFULL*NCH];     // RNA-rounded x
__device__ float g_Wr[4u*1024u*1024u];        // RNA-rounded W_k,W_v,W_g,W_p
__device__ float g_attn_part[8*128*NL*ND];
__device__ float g_attn[128*NL*ND];

// ---------------- helpers -------------------------------------------------
__device__ __forceinline__ float to_tf32(float x) {
    unsigned u;
    asm("cvt.rna.tf32.f32 %0, %1;" : "=r"(u) : "f"(x));
    return __uint_as_float(u);
}

__device__ __forceinline__ uint32_t smem_u32(const void* p) {
    uint32_t a;
    asm("{ .reg .u64 t; cvta.to.shared.u64 t, %1; cvt.u32.u64 %0, t; }"
        : "=r"(a) : "l"(p));
    return a;
}

__device__ __forceinline__ void cp16(uint32_t dst, const float* src) {
    asm volatile("cp.async.cg.shared.global [%0], [%1], 16;"
                 :: "r"(dst), "l"(__cvta_generic_to_global(src)));
}

__device__ __forceinline__ void ldsm4(uint32_t* r, uint32_t a) {
    asm volatile("ldmatrix.sync.aligned.m8n8.x4.shared.b16 {%0,%1,%2,%3}, [%4];"
        : "=r"(r[0]), "=r"(r[1]), "=r"(r[2]), "=r"(r[3]) : "r"(a));
}

__device__ __forceinline__ void mma8(float* c,
    uint32_t a0, uint32_t a1, uint32_t a2, uint32_t a3,
    uint32_t b0, uint32_t b1)
{
    asm volatile(
        "mma.sync.aligned.m16n8k8.row.col.f32.tf32.tf32.f32 "
        "{%0,%1,%2,%3}, {%4,%5,%6,%7}, {%8,%9}, {%0,%1,%2,%3};"
        : "+f"(c[0]), "+f"(c[1]), "+f"(c[2]), "+f"(c[3])
        : "r"(a0), "r"(a1), "r"(a2), "r"(a3), "r"(b0), "r"(b1));
}

// ---------------- tf32 NT GEMM: C[m,n] = sum_k A[map(m),k] * W[n,k] -------
// Block 256x128, 256 threads, warps 4(m) x 2(n), warp tile 64x64.
// KC=32 per stage, 3-stage cp.async ring, ldmatrix fragment loads.
#define STG   49152        // stage bytes: A 256*128 + B 128*128

template<bool REMAP>
__global__ void __launch_bounds__(256) gemm_tc(
    const float* __restrict__ A, const float* __restrict__ W,
    float* __restrict__ C)
{
    extern __shared__ char smem[];
    const uint32_t sb = smem_u32(smem);

    const int tid  = threadIdx.x;
    const int lane = tid & 31, warp = tid >> 5;
    const int wm   = warp >> 1;           // 0..3
    const int wn   = warp & 1;            // 0..1
    const int n0   = blockIdx.x * 128;
    const int m0   = blockIdx.y * 256;

    // ---- loader precompute: thread owns A row tid (8 chunks) + B half-row
    int gm = m0 + tid;
    if (REMAP) gm = ((gm >> 6) << 7) + (gm & 63);
    const float* Arow = A + (size_t)gm * NCH;
    const float* Brow = W + (size_t)(n0 + (tid >> 1)) * NCH;
    const uint32_t adst = sb + (uint32_t)tid * 128u;
    const uint32_t aswz = tid & 7;
    const uint32_t bdst = sb + 32768u + (uint32_t)(tid >> 1) * 128u;
    const int      bc0  = (tid & 1) * 4;
    const uint32_t bswz = (tid >> 1) & 7;

    // ---- ldmatrix per-lane precompute
    const int mq = lane >> 3, lr = lane & 7;
    const int aRow = wm*64 + ((mq & 1) << 3) + lr;
    const int aCp  = mq >> 1;
    const int aSwz = aRow & 7;
    const uint32_t aB = sb + (uint32_t)aRow * 128u;
    const int bRow = wn*64 + ((mq >> 1) << 3) + lr;
    const int bCp  = mq & 1;
    const int bSwz = bRow & 7;
    const uint32_t bB = sb + 32768u + (uint32_t)bRow * 128u;

    float acc[4][8][4];
    #pragma unroll
    for (int i = 0; i < 4; ++i)
        #pragma unroll
        for (int j = 0; j < 8; ++j)
            #pragma unroll
            for (int k = 0; k < 4; ++k) acc[i][j][k] = 0.f;

    // ---- prologue: stages 0..2
    #pragma unroll
    for (int s = 0; s < 3; ++s) {
        const int k0 = s * 32;
        const uint32_t so = (uint32_t)s * STG;
        #pragma unroll
        for (int c = 0; c < 8; ++c)
            cp16(adst + so + (((uint32_t)c ^ aswz) << 4), Arow + k0 + c*4);
        #pragma unroll
        for (int c = 0; c < 4; ++c) {
            const int cc = bc0 + c;
            cp16(bdst + so + (((uint32_t)cc ^ bswz) << 4), Brow + k0 + cc*4);
        }
        asm volatile("cp.async.commit_group;");
    }

    // ---- main loop: 32 stages of KC=32
    for (int it = 0; it < 32; ++it) {
        asm volatile("cp.async.wait_group 2;");
        __syncthreads();

        const uint32_t so = (uint32_t)(it % 3) * STG;
        #pragma unroll
        for (int ks = 0; ks < 4; ++ks) {
            uint32_t af[4][4], bf[8][2];
            #pragma unroll
            for (int i = 0; i < 4; ++i)
                ldsm4(af[i], aB + so + (uint32_t)i*2048u
                             + ((uint32_t)((ks*2 + aCp) ^ aSwz) << 4));
            #pragma unroll
            for (int p = 0; p < 4; ++p)
                ldsm4(&bf[2*p][0], bB + so + (uint32_t)p*2048u
                             + ((uint32_t)((ks*2 + bCp) ^ bSwz) << 4));
            #pragma unroll
            for (int i = 0; i < 4; ++i)
                #pragma unroll
                for (int j = 0; j < 8; ++j)
                    mma8(acc[i][j], af[i][0], af[i][1], af[i][2], af[i][3],
                         bf[j][0], bf[j][1]);
        }
        __syncthreads();

        if (it + 3 < 32) {
            const int k0 = (it + 3) * 32;
            #pragma unroll
            for (int c = 0; c < 8; ++c)
                cp16(adst + so + (((uint32_t)c ^ aswz) << 4), Arow + k0 + c*4);
            #pragma unroll
            for (int c = 0; c < 4; ++c) {
                const int cc = bc0 + c;
                cp16(bdst + so + (((uint32_t)cc ^ bswz) << 4), Brow + k0 + cc*4);
            }
        }
        asm volatile("cp.async.commit_group;");
    }

    // ---- epilogue
    const int g = lane >> 2, q = lane & 3;
    #pragma unroll
    for (int i = 0; i < 4; ++i) {
        const int r = m0 + wm*64 + i*16 + g;
        #pragma unroll
        for (int j = 0; j < 8; ++j) {
            const int c = n0 + wn*64 + j*8 + 2*q;
            *(float2*)&C[(size_t)r*NCH + c] =
                make_float2(acc[i][j][0], acc[i][j][1]);
            *(float2*)&C[(size_t)(r+8)*NCH + c] =
                make_float2(acc[i][j][2], acc[i][j][3]);
        }
    }
}

// ---------------- RNA tf32 pre-rounding ----------------------------------
__global__ void __launch_bounds__(256) round_tf32_k(
    const float4* __restrict__ in, float4* __restrict__ out, int n4)
{
    int i = blockIdx.x*256 + threadIdx.x;
    if (i < n4) {
        float4 v = in[i];
        v.x = to_tf32(v.x); v.y = to_tf32(v.y);
        v.z = to_tf32(v.z); v.w = to_tf32(v.w);
        out[i] = v;
    }
}

// ---------------- rope on selected-token K (in place) --------------------
__global__ void __launch_bounds__(256) rope_kernel(float* __restrict__ K)
{
    int p = blockIdx.x*256 + threadIdx.x;
    int row = p >> 9;
    int r   = p & 511;
    int h   = r >> 5;
    int i   = r & 31;
    int t   = (((row >> 6) & 31) << 7) + (row & 63);
    float inv = expf(-(float)i * 0.28782313662425572f);
    float ang = (float)t * inv;
    float s, c;
    sincosf(ang, &s, &c);
    size_t idx = (size_t)row*NCH + h*ND + 2*i;
    float2 ab = *(float2*)&K[idx];
    float2 o = make_float2(ab.x*c - ab.y*s, ab.x*s + ab.y*c);
    *(float2*)&K[idx] = o;
}

// ---------------- gates softmax (in place) --------------------------------
__global__ void __launch_bounds__(256) gates_softmax(float* __restrict__ G)
{
    const int warp = threadIdx.x >> 5, lane = threadIdx.x & 31;
    const size_t grp = (size_t)blockIdx.x * 8 + warp;
    float* p = G + grp*64 + lane*2;
    float2 v = *(float2*)p;
    float m = fmaxf(v.x, v.y);
    #pragma unroll
    for (int o = 16; o; o >>= 1) m = fmaxf(m, __shfl_xor_sync(~0u, m, o));
    float e0 = expf((v.x - m)*0.125f);
    float e1 = expf((v.y - m)*0.125f);
    float s = e0 + e1;
    #pragma unroll
    for (int o = 16; o; o >>= 1) s += __shfl_xor_sync(~0u, s, o);
    float r = 1.0f / s;
    *(float2*)p = make_float2(e0*r, e1*r);
}

// ---------------- attention core ------------------------------------------
__global__ void __launch_bounds__(256) attn_kernel(
    const float* __restrict__ Kh, const float* __restrict__ Vh,
    const float* __restrict__ LQ, float* __restrict__ Part)
{
    __shared__ float qt[4096];
    __shared__ float KV[4096];
    __shared__ float Ss[4096];

    const int tid  = threadIdx.x;
    const int bh   = blockIdx.y;
    const int b    = bh >> 4, h = bh & 15;
    const int gx   = blockIdx.x;
    const int lt   = tid >> 4, ct = tid & 15;
    const int lane = tid & 31, warp = tid >> 5;

    #pragma unroll
    for (int it = 0; it < 16; ++it) {
        int e = tid + it*256;
        int d = e & 63, l = e >> 6;
        float v = LQ[(size_t)(l*NH + h)*ND + d];
        qt[d*64 + ((((l>>2) ^ (d & 15)) << 2) | (l & 3))] = v;
    }

    float att[4][4];
    #pragma unroll
    for (int i=0;i<4;i++)
        #pragma unroll
        for (int j=0;j<4;j++) att[i][j]=0.f;

    float4* KVv = (float4*)KV;
    const float4* qtv = (const float4*)qt;
    __syncthreads();

    for (int nn = 0; nn < 4; ++nn) {
        const int n = gx*4 + nn;
        const size_t rowbase = ((size_t)(b*NCHK + n)*64)*NCH + (size_t)h*ND;

        #pragma unroll
        for (int it = 0; it < 16; ++it) {
            int e = tid + it*256;
            int d = e & 63, c = e >> 6;
            KV[d*64 + ((((c>>2) ^ (d & 15)) << 2) | (c & 3))] =
                Kh[rowbase + (size_t)c*NCH + d];
        }
        __syncthreads();

        float s[4][4];
        #pragma unroll
        for (int i=0;i<4;i++)
            #pragma unroll
            for (int j=0;j<4;j++) s[i][j]=0.f;
        #pragma unroll 8
        for (int d = 0; d < 64; ++d) {
            float4 qv = qtv[d*16 + (lt ^ (d & 15))];
            float4 kv = KVv[d*16 + (ct ^ (d & 15))];
            s[0][0]+=qv.x*kv.x; s[0][1]+=qv.x*kv.y; s[0][2]+=qv.x*kv.z; s[0][3]+=qv.x*kv.w;
            s[1][0]+=qv.y*kv.x; s[1][1]+=qv.y*kv.y; s[1][2]+=qv.y*kv.z; s[1][3]+=qv.y*kv.w;
            s[2][0]+=qv.z*kv.x; s[2][1]+=qv.z*kv.y; s[2][2]+=qv.z*kv.z; s[2][3]+=qv.z*kv.w;
            s[3][0]+=qv.w*kv.x; s[3][1]+=qv.w*kv.y; s[3][2]+=qv.w*kv.z; s[3][3]+=qv.w*kv.w;
        }
        #pragma unroll
        for (int i=0;i<4;i++) {
            float4 o = make_float4(s[i][0]*0.125f, s[i][1]*0.125f,
                                   s[i][2]*0.125f, s[i][3]*0.125f);
            *(float4*)&Ss[(lt*4+i)*64 + ct*4] = o;
        }
        __syncthreads();

        #pragma unroll
        for (int it = 0; it < 16; ++it) {
            int e = tid + it*256;
            int d = e & 63, c = e >> 6;
            KV[c*64 + d] = Vh[rowbase + (size_t)c*NCH + d];
        }

        #pragma unroll
        for (int rr = 0; rr < 8; ++rr) {
            const int l = warp*8 + rr;
            float v0 = Ss[l*64 + lane];
            float v1 = Ss[l*64 + 32 + lane];
            const bool m0 = (lane <= l);
            const bool m1 = (32 + lane <= l);
            float mx = fmaxf(m0 ? v0 : -1e30f, m1 ? v1 : -1e30f);
            #pragma unroll
            for (int o = 16; o; o >>= 1) mx = fmaxf(mx, __shfl_xor_sync(~0u, mx, o));
            float e0 = m0 ? expf(v0 - mx) : 0.f;
            float e1 = m1 ? expf(v1 - mx) : 0.f;
            float sm = e0 + e1;
            #pragma unroll
            for (int o = 16; o; o >>= 1) sm += __shfl_xor_sync(~0u, sm, o);
            float r = 1.0f / sm;
            Ss[l*64 + lane]      = e0*r;
            Ss[l*64 + 32 + lane] = e1*r;
        }
        __syncthreads();

        #pragma unroll 8
        for (int c = 0; c < 64; ++c) {
            float4 vv = KVv[c*16 + ct];
            float p0 = Ss[(lt*4+0)*64 + c];
            float p1 = Ss[(lt*4+1)*64 + c];
            float p2 = Ss[(lt*4+2)*64 + c];
            float p3 = Ss[(lt*4+3)*64 + c];
            att[0][0]+=p0*vv.x; att[0][1]+=p0*vv.y; att[0][2]+=p0*vv.z; att[0][3]+=p0*vv.w;
            att[1][0]+=p1*vv.x; att[1][1]+=p1*vv.y; att[1][2]+=p1*vv.z; att[1][3]+=p1*vv.w;
            att[2][0]+=p2*vv.x; att[2][1]+=p2*vv.y; att[2][2]+=p2*vv.z; att[2][3]+=p2*vv.w;
            att[3][0]+=p3*vv.x; att[3][1]+=p3*vv.y; att[3][2]+=p3*vv.z; att[3][3]+=p3*vv.w;
        }
        __syncthreads();
    }

    const size_t obase = ((size_t)(gx*128 + bh))*4096;
    #pragma unroll
    for (int i = 0; i < 4; ++i) {
        float4 o = make_float4(att[i][0], att[i][1], att[i][2], att[i][3]);
        *(float4*)&Part[obase + (lt*4+i)*64 + ct*4] = o;
    }
}

__global__ void __launch_bounds__(256) reduce_attn(
    const float* __restrict__ Part, float* __restrict__ Attn)
{
    int e = blockIdx.x*256 + threadIdx.x;
    float s = 0.f;
    #pragma unroll
    for (int g = 0; g < 8; ++g) s += Part[(size_t)g*524288 + e];
    Attn[e] = s;
}

// ---------------- weighted = gates @ attn (RNA-rounded store) -------------
__global__ void __launch_bounds__(128) weighted_kernel(
    const float* __restrict__ G, const float* __restrict__ Attn,
    float* __restrict__ Wt)
{
    __shared__ float gst[64*128];
    __shared__ float as[64*64];

    const int tid = threadIdx.x;
    const int bh  = blockIdx.y;
    const int b   = bh >> 4, h = bh & 15;
    const int t0  = blockIdx.x * 128;

    #pragma unroll
    for (int it = 0; it < 32; ++it) {
        int e = tid + it*128;
        as[e] = Attn[(size_t)bh*4096 + e];
    }
    #pragma unroll
    for (int it = 0; it < 64; ++it) {
        int e = tid + it*128;
        int tt = e >> 6, l = e & 63;
        float v = G[((size_t)(b*NTOK + t0 + tt))*NCH + h*ND + l];
        gst[l*128 + ((((tt>>3) ^ (l & 15)) << 3) | (tt & 7))] = v;
    }
    __syncthreads();

    const int tg = tid >> 3;
    const int dg = tid & 7;
    float acc[8][8];
    #pragma unroll
    for (int i=0;i<8;i++)
        #pragma unroll
        for (int j=0;j<8;j++) acc[i][j]=0.f;

    const float4* asv = (const float4*)as;
    const float4* gv  = (const float4*)gst;
    #pragma unroll 4
    for (int l = 0; l < 64; ++l) {
        const int gi = l*32 + ((tg ^ (l & 15)) << 1);
        float4 g0 = gv[gi], g1 = gv[gi+1];
        float4 a0 = asv[l*16 + dg*2], a1 = asv[l*16 + dg*2 + 1];
        float gg[8] = {g0.x,g0.y,g0.z,g0.w,g1.x,g1.y,g1.z,g1.w};
        #pragma unroll
        for (int i = 0; i < 8; ++i) {
            acc[i][0]+=gg[i]*a0.x; acc[i][1]+=gg[i]*a0.y;
            acc[i][2]+=gg[i]*a0.z; acc[i][3]+=gg[i]*a0.w;
            acc[i][4]+=gg[i]*a1.x; acc[i][5]+=gg[i]*a1.y;
            acc[i][6]+=gg[i]*a1.z; acc[i][7]+=gg[i]*a1.w;
        }
    }

    #pragma unroll
    for (int i = 0; i < 8; ++i) {
        const size_t row = (size_t)(b*NTOK + t0 + tg*8 + i);
        *(float4*)&Wt[row*NCH + h*ND + dg*8] =
            make_float4(to_tf32(acc[i][0]), to_tf32(acc[i][1]),
                        to_tf32(acc[i][2]), to_tf32(acc[i][3]));
        *(float4*)&Wt[row*NCH + h*ND + dg*8 + 4] =
            make_float4(to_tf32(acc[i][4]), to_tf32(acc[i][5]),
                        to_tf32(acc[i][6]), to_tf32(acc[i][7]));
    }
}

// ---------------- launch ---------------------------------------------------
extern "C" void kernel_launch(void* const* d_in, const int* in_sizes, int n_in,
                              void* d_out, int out_size)
{
    const float* x   = (const float*)d_in[0];
    const float* lq  = (const float*)d_in[1];
    const float* W_k = (const float*)d_in[2];
    const float* W_v = (const float*)d_in[3];
    const float* W_g = (const float*)d_in[4];
    const float* W_p = (const float*)d_in[5];
    float* out = (float*)d_out;

    float *Kh, *Vh, *G, *Wt, *xr, *Wr, *Part, *Attn;
    cudaGetSymbolAddress((void**)&Kh,   g_Kh);
    cudaGetSymbolAddress((void**)&Vh,   g_Vh);
    cudaGetSymbolAddress((void**)&G,    g_G);
    cudaGetSymbolAddress((void**)&Wt,   g_Wt);
    cudaGetSymbolAddress((void**)&xr,   g_xr);
    cudaGetSymbolAddress((void**)&Wr,   g_Wr);
    cudaGetSymbolAddress((void**)&Part, g_attn_part);
    cudaGetSymbolAddress((void**)&Attn, g_attn);

    const int SMEM = 3 * STG;   // 144 KB
    cudaFuncSetAttribute(gemm_tc<true >, cudaFuncAttributeMaxDynamicSharedMemorySize, SMEM);
    cudaFuncSetAttribute(gemm_tc<false>, cudaFuncAttributeMaxDynamicSharedMemorySize, SMEM);

    // RNA pre-rounding so HMMA's RZ truncation sees exact tf32 values
    round_tf32_k<<<32768, 256>>>((const float4*)x,   (float4*)xr,               8388608);
    round_tf32_k<<<1024, 256>>>((const float4*)W_k, (float4*)(Wr + 0*1048576), 262144);
    round_tf32_k<<<1024, 256>>>((const float4*)W_v, (float4*)(Wr + 1*1048576), 262144);
    round_tf32_k<<<1024, 256>>>((const float4*)W_g, (float4*)(Wr + 2*1048576), 262144);
    round_tf32_k<<<1024, 256>>>((const float4*)W_p, (float4*)(Wr + 3*1048576), 262144);

    // 6th launch = G GEMM (largest) so ncu -s 5 -c 1 captures a GEMM
    gemm_tc<false><<<dim3(8, 128), 256, SMEM>>>(xr, Wr + 2*1048576, G);
    gemm_tc<true ><<<dim3(8,  64), 256, SMEM>>>(xr, Wr + 0*1048576, Kh);
    gemm_tc<true ><<<dim3(8,  64), 256, SMEM>>>(xr, Wr + 1*1048576, Vh);

    rope_kernel  <<<32768, 256>>>(Kh);
    gates_softmax<<<65536, 256>>>(G);
    attn_kernel  <<<dim3(8, 128), 256>>>(Kh, Vh, lq, Part);
    reduce_attn  <<<2048, 256>>>(Part, Attn);
    weighted_kernel<<<dim3(32, 128), 128>>>(G, Attn, Wt);

    gemm_tc<false><<<dim3(8, 128), 256, SMEM>>>(Wt, Wr + 3*1048576, out);
}

// round 6
// speedup vs baseline: 1.2984x; 1.2984x over previous
#include <cuda_runtime.h>
#include <cstdint>
#include <math.h>

// ---------------- problem constants ----------------
#define NB    8
#define NTOK  4096
#define NCH   1024
#define NH    16
#define NL    64
#define ND    64
#define NCHK  32
#define MSEL  (NB*NCHK*64)        // 16384 selected rows
#define MFULL (NB*NTOK)           // 32768

// ---------------- scratch (device globals) -------------------------------
__device__ float g_Kh[(size_t)MSEL*NCH];
__device__ float g_Vh[(size_t)MSEL*NCH];
__device__ float g_G [(size_t)MFULL*NCH];
__device__ float g_Wt[(size_t)MFULL*NCH];
__device__ float g_xr[(size_t)MFULL*NCH];     // RNA-rounded x
__device__ float g_Wr[4u*1024u*1024u];        // RNA-rounded W_k,W_v,W_g,W_p
__device__ float g_attn_part[8*128*NL*ND];
__device__ float g_attn[128*NL*ND];

// ---------------- helpers -------------------------------------------------
__device__ __forceinline__ float to_tf32(float x) {
    unsigned u;
    asm("cvt.rna.tf32.f32 %0, %1;" : "=r"(u) : "f"(x));
    return __uint_as_float(u);
}

__device__ __forceinline__ uint32_t smem_u32(const void* p) {
    uint32_t a;
    asm("{ .reg .u64 t; cvta.to.shared.u64 t, %1; cvt.u32.u64 %0, t; }"
        : "=r"(a) : "l"(p));
    return a;
}

__device__ __forceinline__ void cp16(uint32_t dst, const float* src) {
    asm volatile("cp.async.cg.shared.global [%0], [%1], 16;"
                 :: "r"(dst), "l"(__cvta_generic_to_global(src)));
}

__device__ __forceinline__ void ldsm4(uint32_t* r, uint32_t a) {
    asm volatile("ldmatrix.sync.aligned.m8n8.x4.shared.b16 {%0,%1,%2,%3}, [%4];"
        : "=r"(r[0]), "=r"(r[1]), "=r"(r[2]), "=r"(r[3]) : "r"(a));
}

__device__ __forceinline__ void mma8(float* c,
    uint32_t a0, uint32_t a1, uint32_t a2, uint32_t a3,
    uint32_t b0, uint32_t b1)
{
    asm volatile(
        "mma.sync.aligned.m16n8k8.row.col.f32.tf32.tf32.f32 "
        "{%0,%1,%2,%3}, {%4,%5,%6,%7}, {%8,%9}, {%0,%1,%2,%3};"
        : "+f"(c[0]), "+f"(c[1]), "+f"(c[2]), "+f"(c[3])
        : "r"(a0), "r"(a1), "r"(a2), "r"(a3), "r"(b0), "r"(b1));
}

// ---------------- tf32 NT GEMM: C[m,n] = sum_k A[map(m),k] * W[n,k] -------
// Block 128x128, 256 threads, warps 2(m) x 4(n), warp tile 64x32.
// KC=32 per stage, 2-stage cp.async ring (64 KB smem -> 2 CTAs/SM).
#define STG 32768        // stage bytes: A 128*128 + B 128*128

template<bool REMAP>
__global__ void __launch_bounds__(256, 2) gemm_tc(
    const float* __restrict__ A, const float* __restrict__ W,
    float* __restrict__ C)
{
    extern __shared__ char smem[];
    const uint32_t sb = smem_u32(smem);

    const int tid  = threadIdx.x;
    const int lane = tid & 31, warp = tid >> 5;
    const int wm   = warp & 1;            // 0..1  (m)
    const int wn   = warp >> 1;           // 0..3  (n)
    const int n0   = blockIdx.x * 128;
    const int m0   = blockIdx.y * 128;

    // ---- loader: each thread owns half an A row and half a B row
    const int lrow = tid >> 1;            // 0..127
    const int lc0  = (tid & 1) * 4;       // chunks 0..3 or 4..7
    int gm = m0 + lrow;
    if (REMAP) gm = ((gm >> 6) << 7) + (gm & 63);
    const float* Arow = A + (size_t)gm * NCH;
    const float* Brow = W + (size_t)(n0 + lrow) * NCH;
    const uint32_t adst = sb + (uint32_t)lrow * 128u;
    const uint32_t bdst = sb + 16384u + (uint32_t)lrow * 128u;
    const uint32_t lswz = (uint32_t)(lrow & 7);

    // ---- ldmatrix per-lane precompute
    const int mq = lane >> 3, lr = lane & 7;
    const int aRow = wm*64 + ((mq & 1) << 3) + lr;
    const int aCp  = mq >> 1;
    const uint32_t aSwz = (uint32_t)(aRow & 7);
    const uint32_t aB = sb + (uint32_t)aRow * 128u;
    const int bRow = wn*32 + ((mq >> 1) << 3) + lr;
    const int bCp  = mq & 1;
    const uint32_t bSwz = (uint32_t)(bRow & 7);
    const uint32_t bB = sb + 16384u + (uint32_t)bRow * 128u;

    float acc[4][4][4];
    #pragma unroll
    for (int i = 0; i < 4; ++i)
        #pragma unroll
        for (int j = 0; j < 4; ++j)
            #pragma unroll
            for (int k = 0; k < 4; ++k) acc[i][j][k] = 0.f;

    // ---- prologue: stages 0..1
    #pragma unroll
    for (int s = 0; s < 2; ++s) {
        const int k0 = s * 32;
        const uint32_t so = (uint32_t)s * STG;
        #pragma unroll
        for (int c = 0; c < 4; ++c) {
            const uint32_t cc = (uint32_t)(lc0 + c);
            cp16(adst + so + ((cc ^ lswz) << 4), Arow + k0 + cc*4);
            cp16(bdst + so + ((cc ^ lswz) << 4), Brow + k0 + cc*4);
        }
        asm volatile("cp.async.commit_group;");
    }

    // ---- main loop: 32 stages of KC=32
    for (int it = 0; it < 32; ++it) {
        asm volatile("cp.async.wait_group 1;");
        __syncthreads();

        const uint32_t so = (uint32_t)(it & 1) * STG;
        #pragma unroll
        for (int ks = 0; ks < 4; ++ks) {
            uint32_t af[4][4], bf[4][2];
            #pragma unroll
            for (int i = 0; i < 4; ++i)
                ldsm4(af[i], aB + so + (uint32_t)i*2048u
                             + (((uint32_t)(ks*2 + aCp) ^ aSwz) << 4));
            #pragma unroll
            for (int p = 0; p < 2; ++p)
                ldsm4(&bf[2*p][0], bB + so + (uint32_t)p*2048u
                             + (((uint32_t)(ks*2 + bCp) ^ bSwz) << 4));
            #pragma unroll
            for (int i = 0; i < 4; ++i)
                #pragma unroll
                for (int j = 0; j < 4; ++j)
                    mma8(acc[i][j], af[i][0], af[i][1], af[i][2], af[i][3],
                         bf[j][0], bf[j][1]);
        }
        __syncthreads();

        if (it + 2 < 32) {
            const int k0 = (it + 2) * 32;
            #pragma unroll
            for (int c = 0; c < 4; ++c) {
                const uint32_t cc = (uint32_t)(lc0 + c);
                cp16(adst + so + ((cc ^ lswz) << 4), Arow + k0 + cc*4);
                cp16(bdst + so + ((cc ^ lswz) << 4), Brow + k0 + cc*4);
            }
        }
        asm volatile("cp.async.commit_group;");
    }

    // ---- epilogue
    const int g = lane >> 2, q = lane & 3;
    #pragma unroll
    for (int i = 0; i < 4; ++i) {
        const int r = m0 + wm*64 + i*16 + g;
        #pragma unroll
        for (int j = 0; j < 4; ++j) {
            const int c = n0 + wn*32 + j*8 + 2*q;
            *(float2*)&C[(size_t)r*NCH + c] =
                make_float2(acc[i][j][0], acc[i][j][1]);
            *(float2*)&C[(size_t)(r+8)*NCH + c] =
                make_float2(acc[i][j][2], acc[i][j][3]);
        }
    }
}

// ---------------- RNA tf32 pre-rounding (proven R4 version) --------------
__global__ void __launch_bounds__(256) round_tf32_k(
    const float4* __restrict__ in, float4* __restrict__ out, int n4)
{
    int i = blockIdx.x*256 + threadIdx.x;
    if (i < n4) {
        float4 v = in[i];
        v.x = to_tf32(v.x); v.y = to_tf32(v.y);
        v.z = to_tf32(v.z); v.w = to_tf32(v.w);
        out[i] = v;
    }
}

// ---------------- rope on selected-token K (in place) --------------------
__global__ void __launch_bounds__(256) rope_kernel(float* __restrict__ K)
{
    int p = blockIdx.x*256 + threadIdx.x;
    int row = p >> 9;
    int r   = p & 511;
    int h   = r >> 5;
    int i   = r & 31;
    int t   = (((row >> 6) & 31) << 7) + (row & 63);
    float inv = expf(-(float)i * 0.28782313662425572f);
    float ang = (float)t * inv;
    float s, c;
    sincosf(ang, &s, &c);
    size_t idx = (size_t)row*NCH + h*ND + 2*i;
    float2 ab = *(float2*)&K[idx];
    float2 o = make_float2(ab.x*c - ab.y*s, ab.x*s + ab.y*c);
    *(float2*)&K[idx] = o;
}

// ---------------- gates softmax (in place) --------------------------------
__global__ void __launch_bounds__(256) gates_softmax(float* __restrict__ G)
{
    const int warp = threadIdx.x >> 5, lane = threadIdx.x & 31;
    const size_t grp = (size_t)blockIdx.x * 8 + warp;
    float* p = G + grp*64 + lane*2;
    float2 v = *(float2*)p;
    float m = fmaxf(v.x, v.y);
    #pragma unroll
    for (int o = 16; o; o >>= 1) m = fmaxf(m, __shfl_xor_sync(~0u, m, o));
    float e0 = expf((v.x - m)*0.125f);
    float e1 = expf((v.y - m)*0.125f);
    float s = e0 + e1;
    #pragma unroll
    for (int o = 16; o; o >>= 1) s += __shfl_xor_sync(~0u, s, o);
    float r = 1.0f / s;
    *(float2*)p = make_float2(e0*r, e1*r);
}

// ---------------- attention core ------------------------------------------
__global__ void __launch_bounds__(256) attn_kernel(
    const float* __restrict__ Kh, const float* __restrict__ Vh,
    const float* __restrict__ LQ, float* __restrict__ Part)
{
    __shared__ float qt[4096];
    __shared__ float KV[4096];
    __shared__ float Ss[4096];

    const int tid  = threadIdx.x;
    const int bh   = blockIdx.y;
    const int b    = bh >> 4, h = bh & 15;
    const int gx   = blockIdx.x;
    const int lt   = tid >> 4, ct = tid & 15;
    const int lane = tid & 31, warp = tid >> 5;

    #pragma unroll
    for (int it = 0; it < 16; ++it) {
        int e = tid + it*256;
        int d = e & 63, l = e >> 6;
        float v = LQ[(size_t)(l*NH + h)*ND + d];
        qt[d*64 + ((((l>>2) ^ (d & 15)) << 2) | (l & 3))] = v;
    }

    float att[4][4];
    #pragma unroll
    for (int i=0;i<4;i++)
        #pragma unroll
        for (int j=0;j<4;j++) att[i][j]=0.f;

    float4* KVv = (float4*)KV;
    const float4* qtv = (const float4*)qt;
    __syncthreads();

    for (int nn = 0; nn < 4; ++nn) {
        const int n = gx*4 + nn;
        const size_t rowbase = ((size_t)(b*NCHK + n)*64)*NCH + (size_t)h*ND;

        #pragma unroll
        for (int it = 0; it < 16; ++it) {
            int e = tid + it*256;
            int d = e & 63, c = e >> 6;
            KV[d*64 + ((((c>>2) ^ (d & 15)) << 2) | (c & 3))] =
                Kh[rowbase + (size_t)c*NCH + d];
        }
        __syncthreads();

        float s[4][4];
        #pragma unroll
        for (int i=0;i<4;i++)
            #pragma unroll
            for (int j=0;j<4;j++) s[i][j]=0.f;
        #pragma unroll 8
        for (int d = 0; d < 64; ++d) {
            float4 qv = qtv[d*16 + (lt ^ (d & 15))];
            float4 kv = KVv[d*16 + (ct ^ (d & 15))];
            s[0][0]+=qv.x*kv.x; s[0][1]+=qv.x*kv.y; s[0][2]+=qv.x*kv.z; s[0][3]+=qv.x*kv.w;
            s[1][0]+=qv.y*kv.x; s[1][1]+=qv.y*kv.y; s[1][2]+=qv.y*kv.z; s[1][3]+=qv.y*kv.w;
            s[2][0]+=qv.z*kv.x; s[2][1]+=qv.z*kv.y; s[2][2]+=qv.z*kv.z; s[2][3]+=qv.z*kv.w;
            s[3][0]+=qv.w*kv.x; s[3][1]+=qv.w*kv.y; s[3][2]+=qv.w*kv.z; s[3][3]+=qv.w*kv.w;
        }
        #pragma unroll
        for (int i=0;i<4;i++) {
            float4 o = make_float4(s[i][0]*0.125f, s[i][1]*0.125f,
                                   s[i][2]*0.125f, s[i][3]*0.125f);
            *(float4*)&Ss[(lt*4+i)*64 + ct*4] = o;
        }
        __syncthreads();

        #pragma unroll
        for (int it = 0; it < 16; ++it) {
            int e = tid + it*256;
            int d = e & 63, c = e >> 6;
            KV[c*64 + d] = Vh[rowbase + (size_t)c*NCH + d];
        }

        #pragma unroll
        for (int rr = 0; rr < 8; ++rr) {
            const int l = warp*8 + rr;
            float v0 = Ss[l*64 + lane];
            float v1 = Ss[l*64 + 32 + lane];
            const bool m0 = (lane <= l);
            const bool m1 = (32 + lane <= l);
            float mx = fmaxf(m0 ? v0 : -1e30f, m1 ? v1 : -1e30f);
            #pragma unroll
            for (int o = 16; o; o >>= 1) mx = fmaxf(mx, __shfl_xor_sync(~0u, mx, o));
            float e0 = m0 ? expf(v0 - mx) : 0.f;
            float e1 = m1 ? expf(v1 - mx) : 0.f;
            float sm = e0 + e1;
            #pragma unroll
            for (int o = 16; o; o >>= 1) sm += __shfl_xor_sync(~0u, sm, o);
            float r = 1.0f / sm;
            Ss[l*64 + lane]      = e0*r;
            Ss[l*64 + 32 + lane] = e1*r;
        }
        __syncthreads();

        #pragma unroll 8
        for (int c = 0; c < 64; ++c) {
            float4 vv = KVv[c*16 + ct];
            float p0 = Ss[(lt*4+0)*64 + c];
            float p1 = Ss[(lt*4+1)*64 + c];
            float p2 = Ss[(lt*4+2)*64 + c];
            float p3 = Ss[(lt*4+3)*64 + c];
            att[0][0]+=p0*vv.x; att[0][1]+=p0*vv.y; att[0][2]+=p0*vv.z; att[0][3]+=p0*vv.w;
            att[1][0]+=p1*vv.x; att[1][1]+=p1*vv.y; att[1][2]+=p1*vv.z; att[1][3]+=p1*vv.w;
            att[2][0]+=p2*vv.x; att[2][1]+=p2*vv.y; att[2][2]+=p2*vv.z; att[2][3]+=p2*vv.w;
            att[3][0]+=p3*vv.x; att[3][1]+=p3*vv.y; att[3][2]+=p3*vv.z; att[3][3]+=p3*vv.w;
        }
        __syncthreads();
    }

    const size_t obase = ((size_t)(gx*128 + bh))*4096;
    #pragma unroll
    for (int i = 0; i < 4; ++i) {
        float4 o = make_float4(att[i][0], att[i][1], att[i][2], att[i][3]);
        *(float4*)&Part[obase + (lt*4+i)*64 + ct*4] = o;
    }
}

__global__ void __launch_bounds__(256) reduce_attn(
    const float* __restrict__ Part, float* __restrict__ Attn)
{
    int e = blockIdx.x*256 + threadIdx.x;
    float s = 0.f;
    #pragma unroll
    for (int g = 0; g < 8; ++g) s += Part[(size_t)g*524288 + e];
    Attn[e] = s;
}

// ---------------- weighted = gates @ attn (RNA-rounded store) -------------
__global__ void __launch_bounds__(128) weighted_kernel(
    const float* __restrict__ G, const float* __restrict__ Attn,
    float* __restrict__ Wt)
{
    __shared__ float gst[64*128];
    __shared__ float as[64*64];

    const int tid = threadIdx.x;
    const int bh  = blockIdx.y;
    const int b   = bh >> 4, h = bh & 15;
    const int t0  = blockIdx.x * 128;

    #pragma unroll
    for (int it = 0; it < 32; ++it) {
        int e = tid + it*128;
        as[e] = Attn[(size_t)bh*4096 + e];
    }
    #pragma unroll
    for (int it = 0; it < 64; ++it) {
        int e = tid + it*128;
        int tt = e >> 6, l = e & 63;
        float v = G[((size_t)(b*NTOK + t0 + tt))*NCH + h*ND + l];
        gst[l*128 + ((((tt>>3) ^ (l & 15)) << 3) | (tt & 7))] = v;
    }
    __syncthreads();

    const int tg = tid >> 3;
    const int dg = tid & 7;
    float acc[8][8];
    #pragma unroll
    for (int i=0;i<8;i++)
        #pragma unroll
        for (int j=0;j<8;j++) acc[i][j]=0.f;

    const float4* asv = (const float4*)as;
    const float4* gv  = (const float4*)gst;
    #pragma unroll 4
    for (int l = 0; l < 64; ++l) {
        const int gi = l*32 + ((tg ^ (l & 15)) << 1);
        float4 g0 = gv[gi], g1 = gv[gi+1];
        float4 a0 = asv[l*16 + dg*2], a1 = asv[l*16 + dg*2 + 1];
        float gg[8] = {g0.x,g0.y,g0.z,g0.w,g1.x,g1.y,g1.z,g1.w};
        #pragma unroll
        for (int i = 0; i < 8; ++i) {
            acc[i][0]+=gg[i]*a0.x; acc[i][1]+=gg[i]*a0.y;
            acc[i][2]+=gg[i]*a0.z; acc[i][3]+=gg[i]*a0.w;
            acc[i][4]+=gg[i]*a1.x; acc[i][5]+=gg[i]*a1.y;
            acc[i][6]+=gg[i]*a1.z; acc[i][7]+=gg[i]*a1.w;
        }
    }

    #pragma unroll
    for (int i = 0; i < 8; ++i) {
        const size_t row = (size_t)(b*NTOK + t0 + tg*8 + i);
        *(float4*)&Wt[row*NCH + h*ND + dg*8] =
            make_float4(to_tf32(acc[i][0]), to_tf32(acc[i][1]),
                        to_tf32(acc[i][2]), to_tf32(acc[i][3]));
        *(float4*)&Wt[row*NCH + h*ND + dg*8 + 4] =
            make_float4(to_tf32(acc[i][4]), to_tf32(acc[i][5]),
                        to_tf32(acc[i][6]), to_tf32(acc[i][7]));
    }
}

// ---------------- launch ---------------------------------------------------
extern "C" void kernel_launch(void* const* d_in, const int* in_sizes, int n_in,
                              void* d_out, int out_size)
{
    const float* x   = (const float*)d_in[0];
    const float* lq  = (const float*)d_in[1];
    const float* W_k = (const float*)d_in[2];
    const float* W_v = (const float*)d_in[3];
    const float* W_g = (const float*)d_in[4];
    const float* W_p = (const float*)d_in[5];
    float* out = (float*)d_out;

    float *Kh, *Vh, *G, *Wt, *xr, *Wr, *Part, *Attn;
    cudaGetSymbolAddress((void**)&Kh,   g_Kh);
    cudaGetSymbolAddress((void**)&Vh,   g_Vh);
    cudaGetSymbolAddress((void**)&G,    g_G);
    cudaGetSymbolAddress((void**)&Wt,   g_Wt);
    cudaGetSymbolAddress((void**)&xr,   g_xr);
    cudaGetSymbolAddress((void**)&Wr,   g_Wr);
    cudaGetSymbolAddress((void**)&Part, g_attn_part);
    cudaGetSymbolAddress((void**)&Attn, g_attn);

    const int SMEM = 2 * STG;   // 64 KB -> 2 CTAs/SM
    cudaFuncSetAttribute(gemm_tc<true >, cudaFuncAttributeMaxDynamicSharedMemorySize, SMEM);
    cudaFuncSetAttribute(gemm_tc<false>, cudaFuncAttributeMaxDynamicSharedMemorySize, SMEM);

    // 0..4: RNA pre-rounding (proven R4 version)
    round_tf32_k<<<32768, 256>>>((const float4*)x,   (float4*)xr,               8388608);
    round_tf32_k<<<1024, 256>>>((const float4*)W_k, (float4*)(Wr + 0*1048576), 262144);
    round_tf32_k<<<1024, 256>>>((const float4*)W_v, (float4*)(Wr + 1*1048576), 262144);
    round_tf32_k<<<1024, 256>>>((const float4*)W_g, (float4*)(Wr + 2*1048576), 262144);
    round_tf32_k<<<1024, 256>>>((const float4*)W_p, (float4*)(Wr + 3*1048576), 262144);

    // 5,6,7: GEMMs back-to-back so ncu -s 5 -c 1 lands on one of them
    gemm_tc<false><<<dim3(8, 256), 256, SMEM>>>(xr, Wr + 2*1048576, G);
    gemm_tc<true ><<<dim3(8, 128), 256, SMEM>>>(xr, Wr + 0*1048576, Kh);
    gemm_tc<true ><<<dim3(8, 128), 256, SMEM>>>(xr, Wr + 1*1048576, Vh);

    // 8..12
    rope_kernel  <<<32768, 256>>>(Kh);
    gates_softmax<<<65536, 256>>>(G);
    attn_kernel  <<<dim3(8, 128), 256>>>(Kh, Vh, lq, Part);
    reduce_attn  <<<2048, 256>>>(Part, Attn);
    weighted_kernel<<<dim3(32, 128), 128>>>(G, Attn, Wt);

    // 13: output projection
    gemm_tc<false><<<dim3(8, 256), 256, SMEM>>>(Wt, Wr + 3*1048576, out);
}

// round 7
// speedup vs baseline: 1.3192x; 1.0160x over previous
#include <cuda_runtime.h>
#include <cstdint>
#include <math.h>

// ---------------- problem constants ----------------
#define NB    8
#define NTOK  4096
#define NCH   1024
#define NH    16
#define NL    64
#define ND    64
#define NCHK  32
#define MSEL  (NB*NCHK*64)        // 16384 selected rows
#define MFULL (NB*NTOK)           // 32768

// ---------------- scratch (device globals) -------------------------------
__device__ float g_Kh[(size_t)MSEL*NCH];
__device__ float g_Vh[(size_t)MSEL*NCH];
__device__ float g_G [(size_t)MFULL*NCH];
__device__ float g_Wt[(size_t)MFULL*NCH];
__device__ float g_xr[(size_t)MFULL*NCH];     // RNA-rounded x
__device__ float g_Wr[4u*1024u*1024u];        // RNA-rounded W_k,W_v,W_g,W_p
__device__ float g_attn_part[8*128*NL*ND];
__device__ float g_attn[128*NL*ND];

// ---------------- helpers -------------------------------------------------
__device__ __forceinline__ float to_tf32(float x) {
    unsigned u;
    asm("cvt.rna.tf32.f32 %0, %1;" : "=r"(u) : "f"(x));
    return __uint_as_float(u);
}

__device__ __forceinline__ uint32_t smem_u32(const void* p) {
    uint32_t a;
    asm("{ .reg .u64 t; cvta.to.shared.u64 t, %1; cvt.u32.u64 %0, t; }"
        : "=r"(a) : "l"(p));
    return a;
}

__device__ __forceinline__ void cp16(uint32_t dst, const float* src) {
    asm volatile("cp.async.cg.shared.global [%0], [%1], 16;"
                 :: "r"(dst), "l"(__cvta_generic_to_global(src)));
}

__device__ __forceinline__ void ldsm4(uint32_t* r, uint32_t a) {
    asm volatile("ldmatrix.sync.aligned.m8n8.x4.shared.b16 {%0,%1,%2,%3}, [%4];"
        : "=r"(r[0]), "=r"(r[1]), "=r"(r[2]), "=r"(r[3]) : "r"(a));
}

__device__ __forceinline__ void mma8(float* c,
    uint32_t a0, uint32_t a1, uint32_t a2, uint32_t a3,
    uint32_t b0, uint32_t b1)
{
    asm volatile(
        "mma.sync.aligned.m16n8k8.row.col.f32.tf32.tf32.f32 "
        "{%0,%1,%2,%3}, {%4,%5,%6,%7}, {%8,%9}, {%0,%1,%2,%3};"
        : "+f"(c[0]), "+f"(c[1]), "+f"(c[2]), "+f"(c[3])
        : "r"(a0), "r"(a1), "r"(a2), "r"(a3), "r"(b0), "r"(b1));
}

// ---------------- tf32 NT GEMM: C[m,n] = sum_k A[map(m),k] * W[n,k] -------
// Block 128x128, 256 threads, warps 2(m) x 4(n), warp tile 64x32.
// KC=32 per stage, 3-stage cp.async ring, ONE barrier per iteration.
#define STG 32768        // stage bytes: A 128*128 + B 128*128

template<bool REMAP>
__global__ void __launch_bounds__(256, 2) gemm_tc(
    const float* __restrict__ A, const float* __restrict__ W,
    float* __restrict__ C)
{
    extern __shared__ char smem[];
    const uint32_t sb = smem_u32(smem);

    const int tid  = threadIdx.x;
    const int lane = tid & 31, warp = tid >> 5;
    const int wm   = warp & 1;            // 0..1  (m)
    const int wn   = warp >> 1;           // 0..3  (n)
    const int n0   = blockIdx.x * 128;
    const int m0   = blockIdx.y * 128;

    // ---- loader: each thread owns half an A row and half a B row
    const int lrow = tid >> 1;            // 0..127
    const int lc0  = (tid & 1) * 4;       // chunks 0..3 or 4..7
    int gm = m0 + lrow;
    if (REMAP) gm = ((gm >> 6) << 7) + (gm & 63);
    const float* Arow = A + (size_t)gm * NCH;
    const float* Brow = W + (size_t)(n0 + lrow) * NCH;
    const uint32_t adst = sb + (uint32_t)lrow * 128u;
    const uint32_t bdst = sb + 16384u + (uint32_t)lrow * 128u;
    const uint32_t lswz = (uint32_t)(lrow & 7);

    // ---- ldmatrix per-lane precompute
    const int mq = lane >> 3, lr = lane & 7;
    const int aRow = wm*64 + ((mq & 1) << 3) + lr;
    const int aCp  = mq >> 1;
    const uint32_t aSwz = (uint32_t)(aRow & 7);
    const uint32_t aB = sb + (uint32_t)aRow * 128u;
    const int bRow = wn*32 + ((mq >> 1) << 3) + lr;
    const int bCp  = mq & 1;
    const uint32_t bSwz = (uint32_t)(bRow & 7);
    const uint32_t bB = sb + 16384u + (uint32_t)bRow * 128u;

    float acc[4][4][4];
    #pragma unroll
    for (int i = 0; i < 4; ++i)
        #pragma unroll
        for (int j = 0; j < 4; ++j)
            #pragma unroll
            for (int k = 0; k < 4; ++k) acc[i][j][k] = 0.f;

    // ---- prologue: stages 0..1 (groups G0, G1)
    #pragma unroll
    for (int s = 0; s < 2; ++s) {
        const int k0 = s * 32;
        const uint32_t so = (uint32_t)s * STG;
        #pragma unroll
        for (int c = 0; c < 4; ++c) {
            const uint32_t cc = (uint32_t)(lc0 + c);
            cp16(adst + so + ((cc ^ lswz) << 4), Arow + k0 + cc*4);
            cp16(bdst + so + ((cc ^ lswz) << 4), Brow + k0 + cc*4);
        }
        asm volatile("cp.async.commit_group;");
    }

    // ---- main loop: 32 stages of KC=32, ONE __syncthreads per iteration.
    // Iter k: wait stage k resident; barrier (also proves all warps finished
    // reading buf (k-1)%3 in iter k-1); prefetch stage k+2 into that buffer.
    uint32_t so_r = 0;                    // (k)%3 * STG
    uint32_t so_w = 2u * STG;             // (k+2)%3 * STG
    for (int it = 0; it < 32; ++it) {
        asm volatile("cp.async.wait_group 1;");
        __syncthreads();

        if (it + 2 < 32) {
            const int k0 = (it + 2) * 32;
            #pragma unroll
            for (int c = 0; c < 4; ++c) {
                const uint32_t cc = (uint32_t)(lc0 + c);
                cp16(adst + so_w + ((cc ^ lswz) << 4), Arow + k0 + cc*4);
                cp16(bdst + so_w + ((cc ^ lswz) << 4), Brow + k0 + cc*4);
            }
        }
        asm volatile("cp.async.commit_group;");

        const uint32_t so = so_r;
        #pragma unroll
        for (int ks = 0; ks < 4; ++ks) {
            uint32_t af[4][4], bf[4][2];
            #pragma unroll
            for (int i = 0; i < 4; ++i)
                ldsm4(af[i], aB + so + (uint32_t)i*2048u
                             + (((uint32_t)(ks*2 + aCp) ^ aSwz) << 4));
            #pragma unroll
            for (int p = 0; p < 2; ++p)
                ldsm4(&bf[2*p][0], bB + so + (uint32_t)p*2048u
                             + (((uint32_t)(ks*2 + bCp) ^ bSwz) << 4));
            #pragma unroll
            for (int i = 0; i < 4; ++i)
                #pragma unroll
                for (int j = 0; j < 4; ++j)
                    mma8(acc[i][j], af[i][0], af[i][1], af[i][2], af[i][3],
                         bf[j][0], bf[j][1]);
        }

        so_r = (so_r == 2u*STG) ? 0u : so_r + STG;
        so_w = (so_w == 2u*STG) ? 0u : so_w + STG;
    }

    // ---- epilogue
    const int g = lane >> 2, q = lane & 3;
    #pragma unroll
    for (int i = 0; i < 4; ++i) {
        const int r = m0 + wm*64 + i*16 + g;
        #pragma unroll
        for (int j = 0; j < 4; ++j) {
            const int c = n0 + wn*32 + j*8 + 2*q;
            *(float2*)&C[(size_t)r*NCH + c] =
                make_float2(acc[i][j][0], acc[i][j][1]);
            *(float2*)&C[(size_t)(r+8)*NCH + c] =
                make_float2(acc[i][j][2], acc[i][j][3]);
        }
    }
}

// ---------------- RNA tf32 pre-rounding ----------------------------------
__global__ void __launch_bounds__(256) round_tf32_k(
    const float4* __restrict__ in, float4* __restrict__ out, int n4)
{
    int i = blockIdx.x*256 + threadIdx.x;
    if (i < n4) {
        float4 v = in[i];
        v.x = to_tf32(v.x); v.y = to_tf32(v.y);
        v.z = to_tf32(v.z); v.w = to_tf32(v.w);
        out[i] = v;
    }
}

// ---------------- rope on selected-token K (in place) --------------------
__global__ void __launch_bounds__(256) rope_kernel(float* __restrict__ K)
{
    int p = blockIdx.x*256 + threadIdx.x;
    int row = p >> 9;
    int r   = p & 511;
    int h   = r >> 5;
    int i   = r & 31;
    int t   = (((row >> 6) & 31) << 7) + (row & 63);
    float inv = expf(-(float)i * 0.28782313662425572f);
    float ang = (float)t * inv;
    float s, c;
    sincosf(ang, &s, &c);
    size_t idx = (size_t)row*NCH + h*ND + 2*i;
    float2 ab = *(float2*)&K[idx];
    float2 o = make_float2(ab.x*c - ab.y*s, ab.x*s + ab.y*c);
    *(float2*)&K[idx] = o;
}

// ---------------- gates softmax (in place) --------------------------------
__global__ void __launch_bounds__(256) gates_softmax(float* __restrict__ G)
{
    const int warp = threadIdx.x >> 5, lane = threadIdx.x & 31;
    const size_t grp = (size_t)blockIdx.x * 8 + warp;
    float* p = G + grp*64 + lane*2;
    float2 v = *(float2*)p;
    float m = fmaxf(v.x, v.y);
    #pragma unroll
    for (int o = 16; o; o >>= 1) m = fmaxf(m, __shfl_xor_sync(~0u, m, o));
    float e0 = expf((v.x - m)*0.125f);
    float e1 = expf((v.y - m)*0.125f);
    float s = e0 + e1;
    #pragma unroll
    for (int o = 16; o; o >>= 1) s += __shfl_xor_sync(~0u, s, o);
    float r = 1.0f / s;
    *(float2*)p = make_float2(e0*r, e1*r);
}

// ---------------- attention core ------------------------------------------
__global__ void __launch_bounds__(256) attn_kernel(
    const float* __restrict__ Kh, const float* __restrict__ Vh,
    const float* __restrict__ LQ, float* __restrict__ Part)
{
    __shared__ float qt[4096];
    __shared__ float KV[4096];
    __shared__ float Ss[4096];

    const int tid  = threadIdx.x;
    const int bh   = blockIdx.y;
    const int b    = bh >> 4, h = bh & 15;
    const int gx   = blockIdx.x;
    const int lt   = tid >> 4, ct = tid & 15;
    const int lane = tid & 31, warp = tid >> 5;

    #pragma unroll
    for (int it = 0; it < 16; ++it) {
        int e = tid + it*256;
        int d = e & 63, l = e >> 6;
        float v = LQ[(size_t)(l*NH + h)*ND + d];
        qt[d*64 + ((((l>>2) ^ (d & 15)) << 2) | (l & 3))] = v;
    }

    float att[4][4];
    #pragma unroll
    for (int i=0;i<4;i++)
        #pragma unroll
        for (int j=0;j<4;j++) att[i][j]=0.f;

    float4* KVv = (float4*)KV;
    const float4* qtv = (const float4*)qt;
    __syncthreads();

    for (int nn = 0; nn < 4; ++nn) {
        const int n = gx*4 + nn;
        const size_t rowbase = ((size_t)(b*NCHK + n)*64)*NCH + (size_t)h*ND;

        #pragma unroll
        for (int it = 0; it < 16; ++it) {
            int e = tid + it*256;
            int d = e & 63, c = e >> 6;
            KV[d*64 + ((((c>>2) ^ (d & 15)) << 2) | (c & 3))] =
                Kh[rowbase + (size_t)c*NCH + d];
        }
        __syncthreads();

        float s[4][4];
        #pragma unroll
        for (int i=0;i<4;i++)
            #pragma unroll
            for (int j=0;j<4;j++) s[i][j]=0.f;
        #pragma unroll 8
        for (int d = 0; d < 64; ++d) {
            float4 qv = qtv[d*16 + (lt ^ (d & 15))];
            float4 kv = KVv[d*16 + (ct ^ (d & 15))];
            s[0][0]+=qv.x*kv.x; s[0][1]+=qv.x*kv.y; s[0][2]+=qv.x*kv.z; s[0][3]+=qv.x*kv.w;
            s[1][0]+=qv.y*kv.x; s[1][1]+=qv.y*kv.y; s[1][2]+=qv.y*kv.z; s[1][3]+=qv.y*kv.w;
            s[2][0]+=qv.z*kv.x; s[2][1]+=qv.z*kv.y; s[2][2]+=qv.z*kv.z; s[2][3]+=qv.z*kv.w;
            s[3][0]+=qv.w*kv.x; s[3][1]+=qv.w*kv.y; s[3][2]+=qv.w*kv.z; s[3][3]+=qv.w*kv.w;
        }
        #pragma unroll
        for (int i=0;i<4;i++) {
            float4 o = make_float4(s[i][0]*0.125f, s[i][1]*0.125f,
                                   s[i][2]*0.125f, s[i][3]*0.125f);
            *(float4*)&Ss[(lt*4+i)*64 + ct*4] = o;
        }
        __syncthreads();

        #pragma unroll
        for (int it = 0; it < 16; ++it) {
            int e = tid + it*256;
            int d = e & 63, c = e >> 6;
            KV[c*64 + d] = Vh[rowbase + (size_t)c*NCH + d];
        }

        #pragma unroll
        for (int rr = 0; rr < 8; ++rr) {
            const int l = warp*8 + rr;
            float v0 = Ss[l*64 + lane];
            float v1 = Ss[l*64 + 32 + lane];
            const bool m0 = (lane <= l);
            const bool m1 = (32 + lane <= l);
            float mx = fmaxf(m0 ? v0 : -1e30f, m1 ? v1 : -1e30f);
            #pragma unroll
            for (int o = 16; o; o >>= 1) mx = fmaxf(mx, __shfl_xor_sync(~0u, mx, o));
            float e0 = m0 ? expf(v0 - mx) : 0.f;
            float e1 = m1 ? expf(v1 - mx) : 0.f;
            float sm = e0 + e1;
            #pragma unroll
            for (int o = 16; o; o >>= 1) sm += __shfl_xor_sync(~0u, sm, o);
            float r = 1.0f / sm;
            Ss[l*64 + lane]      = e0*r;
            Ss[l*64 + 32 + lane] = e1*r;
        }
        __syncthreads();

        #pragma unroll 8
        for (int c = 0; c < 64; ++c) {
            float4 vv = KVv[c*16 + ct];
            float p0 = Ss[(lt*4+0)*64 + c];
            float p1 = Ss[(lt*4+1)*64 + c];
            float p2 = Ss[(lt*4+2)*64 + c];
            float p3 = Ss[(lt*4+3)*64 + c];
            att[0][0]+=p0*vv.x; att[0][1]+=p0*vv.y; att[0][2]+=p0*vv.z; att[0][3]+=p0*vv.w;
            att[1][0]+=p1*vv.x; att[1][1]+=p1*vv.y; att[1][2]+=p1*vv.z; att[1][3]+=p1*vv.w;
            att[2][0]+=p2*vv.x; att[2][1]+=p2*vv.y; att[2][2]+=p2*vv.z; att[2][3]+=p2*vv.w;
            att[3][0]+=p3*vv.x; att[3][1]+=p3*vv.y; att[3][2]+=p3*vv.z; att[3][3]+=p3*vv.w;
        }
        __syncthreads();
    }

    const size_t obase = ((size_t)(gx*128 + bh))*4096;
    #pragma unroll
    for (int i = 0; i < 4; ++i) {
        float4 o = make_float4(att[i][0], att[i][1], att[i][2], att[i][3]);
        *(float4*)&Part[obase + (lt*4+i)*64 + ct*4] = o;
    }
}

__global__ void __launch_bounds__(256) reduce_attn(
    const float* __restrict__ Part, float* __restrict__ Attn)
{
    int e = blockIdx.x*256 + threadIdx.x;
    float s = 0.f;
    #pragma unroll
    for (int g = 0; g < 8; ++g) s += Part[(size_t)g*524288 + e];
    Attn[e] = s;
}

// ---------------- weighted = gates @ attn (RNA-rounded store) -------------
__global__ void __launch_bounds__(128) weighted_kernel(
    const float* __restrict__ G, const float* __restrict__ Attn,
    float* __restrict__ Wt)
{
    __shared__ float gst[64*128];
    __shared__ float as[64*64];

    const int tid = threadIdx.x;
    const int bh  = blockIdx.y;
    const int b   = bh >> 4, h = bh & 15;
    const int t0  = blockIdx.x * 128;

    #pragma unroll
    for (int it = 0; it < 32; ++it) {
        int e = tid + it*128;
        as[e] = Attn[(size_t)bh*4096 + e];
    }
    #pragma unroll
    for (int it = 0; it < 64; ++it) {
        int e = tid + it*128;
        int tt = e >> 6, l = e & 63;
        float v = G[((size_t)(b*NTOK + t0 + tt))*NCH + h*ND + l];
        gst[l*128 + ((((tt>>3) ^ (l & 15)) << 3) | (tt & 7))] = v;
    }
    __syncthreads();

    const int tg = tid >> 3;
    const int dg = tid & 7;
    float acc[8][8];
    #pragma unroll
    for (int i=0;i<8;i++)
        #pragma unroll
        for (int j=0;j<8;j++) acc[i][j]=0.f;

    const float4* asv = (const float4*)as;
    const float4* gv  = (const float4*)gst;
    #pragma unroll 4
    for (int l = 0; l < 64; ++l) {
        const int gi = l*32 + ((tg ^ (l & 15)) << 1);
        float4 g0 = gv[gi], g1 = gv[gi+1];
        float4 a0 = asv[l*16 + dg*2], a1 = asv[l*16 + dg*2 + 1];
        float gg[8] = {g0.x,g0.y,g0.z,g0.w,g1.x,g1.y,g1.z,g1.w};
        #pragma unroll
        for (int i = 0; i < 8; ++i) {
            acc[i][0]+=gg[i]*a0.x; acc[i][1]+=gg[i]*a0.y;
            acc[i][2]+=gg[i]*a0.z; acc[i][3]+=gg[i]*a0.w;
            acc[i][4]+=gg[i]*a1.x; acc[i][5]+=gg[i]*a1.y;
            acc[i][6]+=gg[i]*a1.z; acc[i][7]+=gg[i]*a1.w;
        }
    }

    #pragma unroll
    for (int i = 0; i < 8; ++i) {
        const size_t row = (size_t)(b*NTOK + t0 + tg*8 + i);
        *(float4*)&Wt[row*NCH + h*ND + dg*8] =
            make_float4(to_tf32(acc[i][0]), to_tf32(acc[i][1]),
                        to_tf32(acc[i][2]), to_tf32(acc[i][3]));
        *(float4*)&Wt[row*NCH + h*ND + dg*8 + 4] =
            make_float4(to_tf32(acc[i][4]), to_tf32(acc[i][5]),
                        to_tf32(acc[i][6]), to_tf32(acc[i][7]));
    }
}

// ---------------- launch ---------------------------------------------------
extern "C" void kernel_launch(void* const* d_in, const int* in_sizes, int n_in,
                              void* d_out, int out_size)
{
    const float* x   = (const float*)d_in[0];
    const float* lq  = (const float*)d_in[1];
    const float* W_k = (const float*)d_in[2];
    const float* W_v = (const float*)d_in[3];
    const float* W_g = (const float*)d_in[4];
    const float* W_p = (const float*)d_in[5];
    float* out = (float*)d_out;

    float *Kh, *Vh, *G, *Wt, *xr, *Wr, *Part, *Attn;
    cudaGetSymbolAddress((void**)&Kh,   g_Kh);
    cudaGetSymbolAddress((void**)&Vh,   g_Vh);
    cudaGetSymbolAddress((void**)&G,    g_G);
    cudaGetSymbolAddress((void**)&Wt,   g_Wt);
    cudaGetSymbolAddress((void**)&xr,   g_xr);
    cudaGetSymbolAddress((void**)&Wr,   g_Wr);
    cudaGetSymbolAddress((void**)&Part, g_attn_part);
    cudaGetSymbolAddress((void**)&Attn, g_attn);

    const int SMEM = 3 * STG;   // 96 KB -> 2 CTAs/SM
    cudaFuncSetAttribute(gemm_tc<true >, cudaFuncAttributeMaxDynamicSharedMemorySize, SMEM);
    cudaFuncSetAttribute(gemm_tc<false>, cudaFuncAttributeMaxDynamicSharedMemorySize, SMEM);

    // indices chosen so the G GEMM is our 5th launch (ncu lands there with
    // the harness's one extra leading launch + -s 5)
    round_tf32_k<<<32768, 256>>>((const float4*)x,   (float4*)xr,               8388608); // 0
    round_tf32_k<<<1024, 256>>>((const float4*)W_g, (float4*)(Wr + 2*1048576), 262144);   // 1
    round_tf32_k<<<1024, 256>>>((const float4*)W_k, (float4*)(Wr + 0*1048576), 262144);   // 2
    round_tf32_k<<<1024, 256>>>((const float4*)W_v, (float4*)(Wr + 1*1048576), 262144);   // 3

    gemm_tc<false><<<dim3(8, 256), 256, SMEM>>>(xr, Wr + 2*1048576, G);   // 4  <- profiled
    gemm_tc<true ><<<dim3(8, 128), 256, SMEM>>>(xr, Wr + 0*1048576, Kh);  // 5
    gemm_tc<true ><<<dim3(8, 128), 256, SMEM>>>(xr, Wr + 1*1048576, Vh);  // 6

    rope_kernel  <<<32768, 256>>>(Kh);                                    // 7
    gates_softmax<<<65536, 256>>>(G);                                     // 8
    attn_kernel  <<<dim3(8, 128), 256>>>(Kh, Vh, lq, Part);               // 9
    reduce_attn  <<<2048, 256>>>(Part, Attn);                             // 10
    weighted_kernel<<<dim3(32, 128), 128>>>(G, Attn, Wt);                 // 11

    round_tf32_k<<<1024, 256>>>((const float4*)W_p, (float4*)(Wr + 3*1048576), 262144);   // 12
    gemm_tc<false><<<dim3(8, 256), 256, SMEM>>>(Wt, Wr + 3*1048576, out); // 13
}

// round 8
// speedup vs baseline: 1.4167x; 1.0739x over previous
#include <cuda_runtime.h>
#include <cstdint>
#include <math.h>

// ---------------- problem constants ----------------
#define NB    8
#define NTOK  4096
#define NCH   1024
#define NH    16
#define NL    64
#define ND    64
#define NCHK  32
#define MSEL  (NB*NCHK*64)        // 16384 selected rows
#define MFULL (NB*NTOK)           // 32768

// ---------------- scratch (device globals) -------------------------------
__device__ float g_Kh[(size_t)MSEL*NCH];
__device__ float g_Vh[(size_t)MSEL*NCH];
__device__ float g_G [(size_t)MFULL*NCH];
__device__ float g_Ut[(size_t)NB*NCH*NCH];    // U transposed: [b][c][h*64+l], tf32
__device__ float g_xr[(size_t)MFULL*NCH];     // RNA-rounded x
__device__ float g_Wr[3u*1024u*1024u];        // RNA-rounded W_k,W_v,W_g
__device__ float g_attn_part[8*128*NL*ND];
__device__ float g_attn[128*NL*ND];

// ---------------- helpers -------------------------------------------------
__device__ __forceinline__ float to_tf32(float x) {
    unsigned u;
    asm("cvt.rna.tf32.f32 %0, %1;" : "=r"(u) : "f"(x));
    return __uint_as_float(u);
}

__device__ __forceinline__ uint32_t smem_u32(const void* p) {
    uint32_t a;
    asm("{ .reg .u64 t; cvta.to.shared.u64 t, %1; cvt.u32.u64 %0, t; }"
        : "=r"(a) : "l"(p));
    return a;
}

__device__ __forceinline__ void cp16(uint32_t dst, const float* src) {
    asm volatile("cp.async.cg.shared.global [%0], [%1], 16;"
                 :: "r"(dst), "l"(__cvta_generic_to_global(src)));
}

__device__ __forceinline__ void ldsm4(uint32_t* r, uint32_t a) {
    asm volatile("ldmatrix.sync.aligned.m8n8.x4.shared.b16 {%0,%1,%2,%3}, [%4];"
        : "=r"(r[0]), "=r"(r[1]), "=r"(r[2]), "=r"(r[3]) : "r"(a));
}

__device__ __forceinline__ void mma8(float* c,
    uint32_t a0, uint32_t a1, uint32_t a2, uint32_t a3,
    uint32_t b0, uint32_t b1)
{
    asm volatile(
        "mma.sync.aligned.m16n8k8.row.col.f32.tf32.tf32.f32 "
        "{%0,%1,%2,%3}, {%4,%5,%6,%7}, {%8,%9}, {%0,%1,%2,%3};"
        : "+f"(c[0]), "+f"(c[1]), "+f"(c[2]), "+f"(c[3])
        : "r"(a0), "r"(a1), "r"(a2), "r"(a3), "r"(b0), "r"(b1));
}

// ---------------- tf32 NT GEMM: C[m,n] = sum_k A[map(m),k] * W[n,k] -------
// Block 128x128, 256 threads, warps 2(m) x 4(n), warp tile 64x32.
// KC=32 per stage, 3-stage cp.async ring, ONE barrier per iteration.
// MODE: 0 plain, 1 remap rows, 2 remap + rope epilogue, 3 batched (z = b).
#define STG 32768        // stage bytes: A 128*128 + B 128*128

template<int MODE>
__global__ void __launch_bounds__(256, 2) gemm_tc(
    const float* __restrict__ A, const float* __restrict__ W,
    float* __restrict__ C)
{
    extern __shared__ char smem[];
    const uint32_t sb = smem_u32(smem);

    const int tid  = threadIdx.x;
    const int lane = tid & 31, warp = tid >> 5;
    const int wm   = warp & 1;            // 0..1  (m)
    const int wn   = warp >> 1;           // 0..3  (n)
    const int n0   = blockIdx.x * 128;
    const int m0   = blockIdx.y * 128;
    const int zb   = (MODE == 3) ? blockIdx.z : 0;
    const int moff = (MODE == 3) ? zb * 4096 : 0;   // row offset in A and C
    const float* Wb = (MODE == 3) ? (W + (size_t)zb * 1048576u) : W;

    // ---- loader: each thread owns half an A row and half a B row
    const int lrow = tid >> 1;            // 0..127
    const int lc0  = (tid & 1) * 4;       // chunks 0..3 or 4..7
    int gm = m0 + lrow;
    if (MODE == 1 || MODE == 2) gm = ((gm >> 6) << 7) + (gm & 63);
    const float* Arow = A + (size_t)(moff + gm) * NCH;
    const float* Brow = Wb + (size_t)(n0 + lrow) * NCH;
    const uint32_t adst = sb + (uint32_t)lrow * 128u;
    const uint32_t bdst = sb + 16384u + (uint32_t)lrow * 128u;
    const uint32_t lswz = (uint32_t)(lrow & 7);

    // ---- ldmatrix per-lane precompute
    const int mq = lane >> 3, lr = lane & 7;
    const int aRow = wm*64 + ((mq & 1) << 3) + lr;
    const int aCp  = mq >> 1;
    const uint32_t aSwz = (uint32_t)(aRow & 7);
    const uint32_t aB = sb + (uint32_t)aRow * 128u;
    const int bRow = wn*32 + ((mq >> 1) << 3) + lr;
    const int bCp  = mq & 1;
    const uint32_t bSwz = (uint32_t)(bRow & 7);
    const uint32_t bB = sb + 16384u + (uint32_t)bRow * 128u;

    float acc[4][4][4];
    #pragma unroll
    for (int i = 0; i < 4; ++i)
        #pragma unroll
        for (int j = 0; j < 4; ++j)
            #pragma unroll
            for (int k = 0; k < 4; ++k) acc[i][j][k] = 0.f;

    // ---- prologue: stages 0..1
    #pragma unroll
    for (int s = 0; s < 2; ++s) {
        const int k0 = s * 32;
        const uint32_t so = (uint32_t)s * STG;
        #pragma unroll
        for (int c = 0; c < 4; ++c) {
            const uint32_t cc = (uint32_t)(lc0 + c);
            cp16(adst + so + ((cc ^ lswz) << 4), Arow + k0 + cc*4);
            cp16(bdst + so + ((cc ^ lswz) << 4), Brow + k0 + cc*4);
        }
        asm volatile("cp.async.commit_group;");
    }

    // ---- main loop
    uint32_t so_r = 0;
    uint32_t so_w = 2u * STG;
    for (int it = 0; it < 32; ++it) {
        asm volatile("cp.async.wait_group 1;");
        __syncthreads();

        if (it + 2 < 32) {
            const int k0 = (it + 2) * 32;
            #pragma unroll
            for (int c = 0; c < 4; ++c) {
                const uint32_t cc = (uint32_t)(lc0 + c);
                cp16(adst + so_w + ((cc ^ lswz) << 4), Arow + k0 + cc*4);
                cp16(bdst + so_w + ((cc ^ lswz) << 4), Brow + k0 + cc*4);
            }
        }
        asm volatile("cp.async.commit_group;");

        const uint32_t so = so_r;
        #pragma unroll
        for (int ks = 0; ks < 4; ++ks) {
            uint32_t af[4][4], bf[4][2];
            #pragma unroll
            for (int i = 0; i < 4; ++i)
                ldsm4(af[i], aB + so + (uint32_t)i*2048u
                             + (((uint32_t)(ks*2 + aCp) ^ aSwz) << 4));
            #pragma unroll
            for (int p = 0; p < 2; ++p)
                ldsm4(&bf[2*p][0], bB + so + (uint32_t)p*2048u
                             + (((uint32_t)(ks*2 + bCp) ^ bSwz) << 4));
            #pragma unroll
            for (int i = 0; i < 4; ++i)
                #pragma unroll
                for (int j = 0; j < 4; ++j)
                    mma8(acc[i][j], af[i][0], af[i][1], af[i][2], af[i][3],
                         bf[j][0], bf[j][1]);
        }

        so_r = (so_r == 2u*STG) ? 0u : so_r + STG;
        so_w = (so_w == 2u*STG) ? 0u : so_w + STG;
    }

    // ---- epilogue
    const int g = lane >> 2, q = lane & 3;
    #pragma unroll
    for (int i = 0; i < 4; ++i) {
        const int r = m0 + wm*64 + i*16 + g;
        if (MODE == 2) {
            // rope: row r -> token t; column pair (c, c+1) -> rotation index
            const int t0 = (((r >> 6) & 31) << 7) + (r & 63);
            const int t1 = t0 + 8;                 // row r+8, same chunk
            #pragma unroll
            for (int j = 0; j < 4; ++j) {
                const int c = n0 + wn*32 + j*8 + 2*q;
                const int ip = (c & 63) >> 1;
                const float inv = expf(-(float)ip * 0.28782313662425572f);
                float s0, c0, s1, c1;
                sincosf((float)t0 * inv, &s0, &c0);
                sincosf((float)t1 * inv, &s1, &c1);
                const float a0 = acc[i][j][0], b0 = acc[i][j][1];
                const float a1 = acc[i][j][2], b1 = acc[i][j][3];
                *(float2*)&C[(size_t)r*NCH + c] =
                    make_float2(a0*c0 - b0*s0, a0*s0 + b0*c0);
                *(float2*)&C[(size_t)(r+8)*NCH + c] =
                    make_float2(a1*c1 - b1*s1, a1*s1 + b1*c1);
            }
        } else {
            #pragma unroll
            for (int j = 0; j < 4; ++j) {
                const int c = n0 + wn*32 + j*8 + 2*q;
                *(float2*)&C[(size_t)(moff + r)*NCH + c] =
                    make_float2(acc[i][j][0], acc[i][j][1]);
                *(float2*)&C[(size_t)(moff + r + 8)*NCH + c] =
                    make_float2(acc[i][j][2], acc[i][j][3]);
            }
        }
    }
}

// ---------------- RNA tf32 pre-rounding ----------------------------------
__global__ void __launch_bounds__(256) round_tf32_k(
    const float4* __restrict__ in, float4* __restrict__ out, int n4)
{
    int i = blockIdx.x*256 + threadIdx.x;
    if (i < n4) {
        float4 v = in[i];
        v.x = to_tf32(v.x); v.y = to_tf32(v.y);
        v.z = to_tf32(v.z); v.w = to_tf32(v.w);
        out[i] = v;
    }
}

// ---------------- gates softmax (in place, tf32-rounded store) ------------
__global__ void __launch_bounds__(256) gates_softmax(float* __restrict__ G)
{
    const int warp = threadIdx.x >> 5, lane = threadIdx.x & 31;
    const size_t grp = (size_t)blockIdx.x * 8 + warp;
    float* p = G + grp*64 + lane*2;
    float2 v = *(float2*)p;
    float m = fmaxf(v.x, v.y);
    #pragma unroll
    for (int o = 16; o; o >>= 1) m = fmaxf(m, __shfl_xor_sync(~0u, m, o));
    float e0 = expf((v.x - m)*0.125f);
    float e1 = expf((v.y - m)*0.125f);
    float s = e0 + e1;
    #pragma unroll
    for (int o = 16; o; o >>= 1) s += __shfl_xor_sync(~0u, s, o);
    float r = 1.0f / s;
    *(float2*)p = make_float2(to_tf32(e0*r), to_tf32(e1*r));
}

// ---------------- attention core ------------------------------------------
__global__ void __launch_bounds__(256) attn_kernel(
    const float* __restrict__ Kh, const float* __restrict__ Vh,
    const float* __restrict__ LQ, float* __restrict__ Part)
{
    __shared__ float qt[4096];
    __shared__ float KV[4096];
    __shared__ float Ss[4096];

    const int tid  = threadIdx.x;
    const int bh   = blockIdx.y;
    const int b    = bh >> 4, h = bh & 15;
    const int gx   = blockIdx.x;
    const int lt   = tid >> 4, ct = tid & 15;
    const int lane = tid & 31, warp = tid >> 5;

    #pragma unroll
    for (int it = 0; it < 16; ++it) {
        int e = tid + it*256;
        int d = e & 63, l = e >> 6;
        float v = LQ[(size_t)(l*NH + h)*ND + d];
        qt[d*64 + ((((l>>2) ^ (d & 15)) << 2) | (l & 3))] = v;
    }

    float att[4][4];
    #pragma unroll
    for (int i=0;i<4;i++)
        #pragma unroll
        for (int j=0;j<4;j++) att[i][j]=0.f;

    float4* KVv = (float4*)KV;
    const float4* qtv = (const float4*)qt;
    __syncthreads();

    for (int nn = 0; nn < 4; ++nn) {
        const int n = gx*4 + nn;
        const size_t rowbase = ((size_t)(b*NCHK + n)*64)*NCH + (size_t)h*ND;

        #pragma unroll
        for (int it = 0; it < 16; ++it) {
            int e = tid + it*256;
            int d = e & 63, c = e >> 6;
            KV[d*64 + ((((c>>2) ^ (d & 15)) << 2) | (c & 3))] =
                Kh[rowbase + (size_t)c*NCH + d];
        }
        __syncthreads();

        float s[4][4];
        #pragma unroll
        for (int i=0;i<4;i++)
            #pragma unroll
            for (int j=0;j<4;j++) s[i][j]=0.f;
        #pragma unroll 8
        for (int d = 0; d < 64; ++d) {
            float4 qv = qtv[d*16 + (lt ^ (d & 15))];
            float4 kv = KVv[d*16 + (ct ^ (d & 15))];
            s[0][0]+=qv.x*kv.x; s[0][1]+=qv.x*kv.y; s[0][2]+=qv.x*kv.z; s[0][3]+=qv.x*kv.w;
            s[1][0]+=qv.y*kv.x; s[1][1]+=qv.y*kv.y; s[1][2]+=qv.y*kv.z; s[1][3]+=qv.y*kv.w;
            s[2][0]+=qv.z*kv.x; s[2][1]+=qv.z*kv.y; s[2][2]+=qv.z*kv.z; s[2][3]+=qv.z*kv.w;
            s[3][0]+=qv.w*kv.x; s[3][1]+=qv.w*kv.y; s[3][2]+=qv.w*kv.z; s[3][3]+=qv.w*kv.w;
        }
        #pragma unroll
        for (int i=0;i<4;i++) {
            float4 o = make_float4(s[i][0]*0.125f, s[i][1]*0.125f,
                                   s[i][2]*0.125f, s[i][3]*0.125f);
            *(float4*)&Ss[(lt*4+i)*64 + ct*4] = o;
        }
        __syncthreads();

        #pragma unroll
        for (int it = 0; it < 16; ++it) {
            int e = tid + it*256;
            int d = e & 63, c = e >> 6;
            KV[c*64 + d] = Vh[rowbase + (size_t)c*NCH + d];
        }

        #pragma unroll
        for (int rr = 0; rr < 8; ++rr) {
            const int l = warp*8 + rr;
            float v0 = Ss[l*64 + lane];
            float v1 = Ss[l*64 + 32 + lane];
            const bool m0 = (lane <= l);
            const bool m1 = (32 + lane <= l);
            float mx = fmaxf(m0 ? v0 : -1e30f, m1 ? v1 : -1e30f);
            #pragma unroll
            for (int o = 16; o; o >>= 1) mx = fmaxf(mx, __shfl_xor_sync(~0u, mx, o));
            float e0 = m0 ? expf(v0 - mx) : 0.f;
            float e1 = m1 ? expf(v1 - mx) : 0.f;
            float sm = e0 + e1;
            #pragma unroll
            for (int o = 16; o; o >>= 1) sm += __shfl_xor_sync(~0u, sm, o);
            float r = 1.0f / sm;
            Ss[l*64 + lane]      = e0*r;
            Ss[l*64 + 32 + lane] = e1*r;
        }
        __syncthreads();

        #pragma unroll 8
        for (int c = 0; c < 64; ++c) {
            float4 vv = KVv[c*16 + ct];
            float p0 = Ss[(lt*4+0)*64 + c];
            float p1 = Ss[(lt*4+1)*64 + c];
            float p2 = Ss[(lt*4+2)*64 + c];
            float p3 = Ss[(lt*4+3)*64 + c];
            att[0][0]+=p0*vv.x; att[0][1]+=p0*vv.y; att[0][2]+=p0*vv.z; att[0][3]+=p0*vv.w;
            att[1][0]+=p1*vv.x; att[1][1]+=p1*vv.y; att[1][2]+=p1*vv.z; att[1][3]+=p1*vv.w;
            att[2][0]+=p2*vv.x; att[2][1]+=p2*vv.y; att[2][2]+=p2*vv.z; att[2][3]+=p2*vv.w;
            att[3][0]+=p3*vv.x; att[3][1]+=p3*vv.y; att[3][2]+=p3*vv.z; att[3][3]+=p3*vv.w;
        }
        __syncthreads();
    }

    const size_t obase = ((size_t)(gx*128 + bh))*4096;
    #pragma unroll
    for (int i = 0; i < 4; ++i) {
        float4 o = make_float4(att[i][0], att[i][1], att[i][2], att[i][3]);
        *(float4*)&Part[obase + (lt*4+i)*64 + ct*4] = o;
    }
}

__global__ void __launch_bounds__(256) reduce_attn(
    const float* __restrict__ Part, float* __restrict__ Attn)
{
    int e = blockIdx.x*256 + threadIdx.x;
    float s = 0.f;
    #pragma unroll
    for (int g = 0; g < 8; ++g) s += Part[(size_t)g*524288 + e];
    Attn[e] = s;
}

// ---------------- U kernel: Ut[b][c][h*64+l] = sum_d attn[bh][l][d]*Wp[c][h*64+d]
// grid (8 cblk, 128 bh), 256 threads, fp32 accumulate, tf32-rounded store.
__global__ void __launch_bounds__(256) u_kernel(
    const float* __restrict__ Attn, const float* __restrict__ Wp,
    float* __restrict__ Ut)
{
    extern __shared__ float us[];          // As 64x68 | Ws 128x68 (floats)
    float4* As4 = (float4*)us;             // stride 17 float4
    float4* Ws4 = (float4*)(us + 64*68);   // stride 17 float4

    const int tid  = threadIdx.x;
    const int cblk = blockIdx.x;
    const int bh   = blockIdx.y;
    const int b    = bh >> 4, h = bh & 15;

    const float4* Af = (const float4*)Attn + (size_t)bh * 1024;
    #pragma unroll
    for (int it = 0; it < 4; ++it) {
        int e = tid + it*256;              // 1024 float4
        int l = e >> 4, d4 = e & 15;
        As4[l*17 + d4] = Af[l*16 + d4];
    }
    const float4* Wf = (const float4*)Wp;
    #pragma unroll
    for (int it = 0; it < 8; ++it) {
        int e = tid + it*256;              // 2048 float4
        int cl = e >> 4, d4 = e & 15;
        Ws4[cl*17 + d4] = Wf[(size_t)(cblk*128 + cl)*256 + h*16 + d4];
    }
    __syncthreads();

    const int cg = tid >> 4;               // 0..15 (8 c each)
    const int lg = tid & 15;               // 0..15 (4 l each)
    float acc[8][4];
    #pragma unroll
    for (int i = 0; i < 8; ++i)
        #pragma unroll
        for (int j = 0; j < 4; ++j) acc[i][j] = 0.f;

    #pragma unroll 4
    for (int d4 = 0; d4 < 16; ++d4) {
        float4 a[4], w[8];
        #pragma unroll
        for (int j = 0; j < 4; ++j) a[j] = As4[(lg*4 + j)*17 + d4];
        #pragma unroll
        for (int i = 0; i < 8; ++i) w[i] = Ws4[(cg*8 + i)*17 + d4];
        #pragma unroll
        for (int i = 0; i < 8; ++i)
            #pragma unroll
            for (int j = 0; j < 4; ++j)
                acc[i][j] += w[i].x*a[j].x + w[i].y*a[j].y
                           + w[i].z*a[j].z + w[i].w*a[j].w;
    }

    #pragma unroll
    for (int i = 0; i < 8; ++i) {
        const int c = cblk*128 + cg*8 + i;
        #pragma unroll
        for (int j = 0; j < 4; ++j) {
            const int l = lg*4 + j;
            Ut[(size_t)b*1048576 + (size_t)c*1024 + h*64 + l] = to_tf32(acc[i][j]);
        }
    }
}

// ---------------- launch ---------------------------------------------------
extern "C" void kernel_launch(void* const* d_in, const int* in_sizes, int n_in,
                              void* d_out, int out_size)
{
    const float* x   = (const float*)d_in[0];
    const float* lq  = (const float*)d_in[1];
    const float* W_k = (const float*)d_in[2];
    const float* W_v = (const float*)d_in[3];
    const float* W_g = (const float*)d_in[4];
    const float* W_p = (const float*)d_in[5];
    float* out = (float*)d_out;

    float *Kh, *Vh, *G, *Ut, *xr, *Wr, *Part, *Attn;
    cudaGetSymbolAddress((void**)&Kh,   g_Kh);
    cudaGetSymbolAddress((void**)&Vh,   g_Vh);
    cudaGetSymbolAddress((void**)&G,    g_G);
    cudaGetSymbolAddress((void**)&Ut,   g_Ut);
    cudaGetSymbolAddress((void**)&xr,   g_xr);
    cudaGetSymbolAddress((void**)&Wr,   g_Wr);
    cudaGetSymbolAddress((void**)&Part, g_attn_part);
    cudaGetSymbolAddress((void**)&Attn, g_attn);

    const int SMEM = 3 * STG;   // 96 KB -> 2 CTAs/SM
    cudaFuncSetAttribute(gemm_tc<0>, cudaFuncAttributeMaxDynamicSharedMemorySize, SMEM);
    cudaFuncSetAttribute(gemm_tc<1>, cudaFuncAttributeMaxDynamicSharedMemorySize, SMEM);
    cudaFuncSetAttribute(gemm_tc<2>, cudaFuncAttributeMaxDynamicSharedMemorySize, SMEM);
    cudaFuncSetAttribute(gemm_tc<3>, cudaFuncAttributeMaxDynamicSharedMemorySize, SMEM);
    const int USMEM = (64*68 + 128*68) * 4;   // 52224 B
    cudaFuncSetAttribute(u_kernel, cudaFuncAttributeMaxDynamicSharedMemorySize, USMEM);

    // rounding
    round_tf32_k<<<32768, 256>>>((const float4*)x,   (float4*)xr,               8388608);
    round_tf32_k<<<1024, 256>>>((const float4*)W_g, (float4*)(Wr + 2*1048576), 262144);
    round_tf32_k<<<1024, 256>>>((const float4*)W_k, (float4*)(Wr + 0*1048576), 262144);
    round_tf32_k<<<1024, 256>>>((const float4*)W_v, (float4*)(Wr + 1*1048576), 262144);

    // GEMMs
    gemm_tc<0><<<dim3(8, 256), 256, SMEM>>>(xr, Wr + 2*1048576, G);   // gates logits
    gemm_tc<2><<<dim3(8, 128), 256, SMEM>>>(xr, Wr + 0*1048576, Kh);  // K + rope
    gemm_tc<1><<<dim3(8, 128), 256, SMEM>>>(xr, Wr + 1*1048576, Vh);  // V

    // attention path
    attn_kernel  <<<dim3(8, 128), 256>>>(Kh, Vh, lq, Part);
    gates_softmax<<<65536, 256>>>(G);
    reduce_attn  <<<2048, 256>>>(Part, Attn);
    u_kernel     <<<dim3(8, 128), 256, USMEM>>>(Attn, W_p, Ut);

    // out[b*4096+t][c] = sum_{hl} gates[row][hl] * Ut[b][c][hl]
    gemm_tc<3><<<dim3(8, 32, 8), 256, SMEM>>>(G, Ut, out);
}

// round 9
// speedup vs baseline: 1.4169x; 1.0002x over previous
#include <cuda_runtime.h>
#include <cstdint>
#include <math.h>

// ---------------- problem constants ----------------
#define NB    8
#define NTOK  4096
#define NCH   1024
#define NH    16
#define NL    64
#define ND    64
#define NCHK  32
#define MSEL  (NB*NCHK*64)        // 16384 selected rows
#define MFULL (NB*NTOK)           // 32768

// ---------------- scratch (device globals) -------------------------------
__device__ float g_Kh[(size_t)MSEL*NCH];
__device__ float g_Vh[(size_t)MSEL*NCH];
__device__ float g_G [(size_t)MFULL*NCH];     // gates (tf32-rounded)
__device__ float g_Ut[(size_t)NB*NCH*NCH];    // U^T: [b][c][h*64+l], tf32
__device__ float g_xr[(size_t)MFULL*NCH];     // RNA-rounded x
__device__ float g_Wr[3u*1024u*1024u];        // RNA-rounded W_k,W_v,W_g
__device__ float g_attn_part[8*128*NL*ND];

// ---------------- helpers -------------------------------------------------
__device__ __forceinline__ float to_tf32(float x) {
    unsigned u;
    asm("cvt.rna.tf32.f32 %0, %1;" : "=r"(u) : "f"(x));
    return __uint_as_float(u);
}

__device__ __forceinline__ uint32_t smem_u32(const void* p) {
    uint32_t a;
    asm("{ .reg .u64 t; cvta.to.shared.u64 t, %1; cvt.u32.u64 %0, t; }"
        : "=r"(a) : "l"(p));
    return a;
}

__device__ __forceinline__ void cp16(uint32_t dst, const float* src) {
    asm volatile("cp.async.cg.shared.global [%0], [%1], 16;"
                 :: "r"(dst), "l"(__cvta_generic_to_global(src)));
}

__device__ __forceinline__ void ldsm4(uint32_t* r, uint32_t a) {
    asm volatile("ldmatrix.sync.aligned.m8n8.x4.shared.b16 {%0,%1,%2,%3}, [%4];"
        : "=r"(r[0]), "=r"(r[1]), "=r"(r[2]), "=r"(r[3]) : "r"(a));
}

__device__ __forceinline__ void mma8(float* c,
    uint32_t a0, uint32_t a1, uint32_t a2, uint32_t a3,
    uint32_t b0, uint32_t b1)
{
    asm volatile(
        "mma.sync.aligned.m16n8k8.row.col.f32.tf32.tf32.f32 "
        "{%0,%1,%2,%3}, {%4,%5,%6,%7}, {%8,%9}, {%0,%1,%2,%3};"
        : "+f"(c[0]), "+f"(c[1]), "+f"(c[2]), "+f"(c[3])
        : "r"(a0), "r"(a1), "r"(a2), "r"(a3), "r"(b0), "r"(b1));
}

// ---------------- tf32 NT GEMM: C[m,n] = sum_k A[map(m),k] * W[n,k] -------
// Block 128x128, 256 threads, warps 2(m) x 4(n), warp tile 64x32.
// KC=32 per stage, 3-stage cp.async ring, ONE barrier per iteration.
// MODE: 0 plain, 1 remap rows, 2 remap + rope epilogue, 3 batched (z = b),
//       4 plain + fused gates-softmax epilogue (tile = 2 heads x 128 tokens)
#define STG 32768        // stage bytes: A 128*128 + B 128*128

template<int MODE>
__global__ void __launch_bounds__(256, 2) gemm_tc(
    const float* __restrict__ A, const float* __restrict__ W,
    float* __restrict__ C)
{
    extern __shared__ char smem[];
    const uint32_t sb = smem_u32(smem);

    const int tid  = threadIdx.x;
    const int lane = tid & 31, warp = tid >> 5;
    const int wm   = warp & 1;            // 0..1  (m)
    const int wn   = warp >> 1;           // 0..3  (n)
    const int n0   = blockIdx.x * 128;
    const int m0   = blockIdx.y * 128;
    const int zb   = (MODE == 3) ? blockIdx.z : 0;
    const int moff = (MODE == 3) ? zb * 4096 : 0;   // row offset in A and C
    const float* Wb = (MODE == 3) ? (W + (size_t)zb * 1048576u) : W;

    // ---- loader: each thread owns half an A row and half a B row
    const int lrow = tid >> 1;            // 0..127
    const int lc0  = (tid & 1) * 4;       // chunks 0..3 or 4..7
    int gm = m0 + lrow;
    if (MODE == 1 || MODE == 2) gm = ((gm >> 6) << 7) + (gm & 63);
    const float* Arow = A + (size_t)(moff + gm) * NCH;
    const float* Brow = Wb + (size_t)(n0 + lrow) * NCH;
    const uint32_t adst = sb + (uint32_t)lrow * 128u;
    const uint32_t bdst = sb + 16384u + (uint32_t)lrow * 128u;
    const uint32_t lswz = (uint32_t)(lrow & 7);

    // ---- ldmatrix per-lane precompute
    const int mq = lane >> 3, lr = lane & 7;
    const int aRow = wm*64 + ((mq & 1) << 3) + lr;
    const int aCp  = mq >> 1;
    const uint32_t aSwz = (uint32_t)(aRow & 7);
    const uint32_t aB = sb + (uint32_t)aRow * 128u;
    const int bRow = wn*32 + ((mq >> 1) << 3) + lr;
    const int bCp  = mq & 1;
    const uint32_t bSwz = (uint32_t)(bRow & 7);
    const uint32_t bB = sb + 16384u + (uint32_t)bRow * 128u;

    float acc[4][4][4];
    #pragma unroll
    for (int i = 0; i < 4; ++i)
        #pragma unroll
        for (int j = 0; j < 4; ++j)
            #pragma unroll
            for (int k = 0; k < 4; ++k) acc[i][j][k] = 0.f;

    // ---- prologue: stages 0..1
    #pragma unroll
    for (int s = 0; s < 2; ++s) {
        const int k0 = s * 32;
        const uint32_t so = (uint32_t)s * STG;
        #pragma unroll
        for (int c = 0; c < 4; ++c) {
            const uint32_t cc = (uint32_t)(lc0 + c);
            cp16(adst + so + ((cc ^ lswz) << 4), Arow + k0 + cc*4);
            cp16(bdst + so + ((cc ^ lswz) << 4), Brow + k0 + cc*4);
        }
        asm volatile("cp.async.commit_group;");
    }

    // ---- main loop
    uint32_t so_r = 0;
    uint32_t so_w = 2u * STG;
    for (int it = 0; it < 32; ++it) {
        asm volatile("cp.async.wait_group 1;");
        __syncthreads();

        if (it + 2 < 32) {
            const int k0 = (it + 2) * 32;
            #pragma unroll
            for (int c = 0; c < 4; ++c) {
                const uint32_t cc = (uint32_t)(lc0 + c);
                cp16(adst + so_w + ((cc ^ lswz) << 4), Arow + k0 + cc*4);
                cp16(bdst + so_w + ((cc ^ lswz) << 4), Brow + k0 + cc*4);
            }
        }
        asm volatile("cp.async.commit_group;");

        const uint32_t so = so_r;
        #pragma unroll
        for (int ks = 0; ks < 4; ++ks) {
            uint32_t af[4][4], bf[4][2];
            #pragma unroll
            for (int i = 0; i < 4; ++i)
                ldsm4(af[i], aB + so + (uint32_t)i*2048u
                             + (((uint32_t)(ks*2 + aCp) ^ aSwz) << 4));
            #pragma unroll
            for (int p = 0; p < 2; ++p)
                ldsm4(&bf[2*p][0], bB + so + (uint32_t)p*2048u
                             + (((uint32_t)(ks*2 + bCp) ^ bSwz) << 4));
            #pragma unroll
            for (int i = 0; i < 4; ++i)
                #pragma unroll
                for (int j = 0; j < 4; ++j)
                    mma8(acc[i][j], af[i][0], af[i][1], af[i][2], af[i][3],
                         bf[j][0], bf[j][1]);
        }

        so_r = (so_r == 2u*STG) ? 0u : so_r + STG;
        so_w = (so_w == 2u*STG) ? 0u : so_w + STG;
    }

    // ---- epilogue
    const int g = lane >> 2, q = lane & 3;
    if (MODE == 4) {
        // fused gates softmax: stage accs to smem, softmax each 64-group.
        asm volatile("cp.async.wait_group 0;");   // quiesce pending copies
        __syncthreads();                          // stage buffers now free
        float* eb = (float*)smem;                 // 128 x 132 floats
        #pragma unroll
        for (int i = 0; i < 4; ++i) {
            const int r = wm*64 + i*16 + g;
            #pragma unroll
            for (int j = 0; j < 4; ++j) {
                const int c = wn*32 + j*8 + 2*q;
                eb[r*132 + c]       = acc[i][j][0];
                eb[r*132 + c + 1]   = acc[i][j][1];
                eb[(r+8)*132 + c]   = acc[i][j][2];
                eb[(r+8)*132 + c+1] = acc[i][j][3];
            }
        }
        __syncthreads();
        // thread t: token row = t>>1, head half = t&1 (64 logits)
        const int row = tid >> 1, half = tid & 1;
        const float* src = eb + row*132 + half*64;
        float mx = -1e30f;
        #pragma unroll 8
        for (int k = 0; k < 64; ++k) mx = fmaxf(mx, src[k]);
        mx *= 0.125f;
        float e[64];
        float sm = 0.f;
        #pragma unroll 8
        for (int k = 0; k < 64; ++k) {
            e[k] = expf(src[k]*0.125f - mx);
            sm += e[k];
        }
        const float rs = 1.0f / sm;
        float* dst = C + (size_t)(m0 + row)*NCH + n0 + half*64;
        #pragma unroll
        for (int k4 = 0; k4 < 16; ++k4) {
            *(float4*)(dst + k4*4) = make_float4(
                to_tf32(e[k4*4+0]*rs), to_tf32(e[k4*4+1]*rs),
                to_tf32(e[k4*4+2]*rs), to_tf32(e[k4*4+3]*rs));
        }
        return;
    }
    #pragma unroll
    for (int i = 0; i < 4; ++i) {
        const int r = m0 + wm*64 + i*16 + g;
        if (MODE == 2) {
            // rope: row r -> token t; column pair (c, c+1) -> rotation index
            const int t0 = (((r >> 6) & 31) << 7) + (r & 63);
            const int t1 = t0 + 8;                 // row r+8, same chunk
            #pragma unroll
            for (int j = 0; j < 4; ++j) {
                const int c = n0 + wn*32 + j*8 + 2*q;
                const int ip = (c & 63) >> 1;
                const float inv = expf(-(float)ip * 0.28782313662425572f);
                float s0, c0, s1, c1;
                sincosf((float)t0 * inv, &s0, &c0);
                sincosf((float)t1 * inv, &s1, &c1);
                const float a0 = acc[i][j][0], b0 = acc[i][j][1];
                const float a1 = acc[i][j][2], b1 = acc[i][j][3];
                *(float2*)&C[(size_t)r*NCH + c] =
                    make_float2(a0*c0 - b0*s0, a0*s0 + b0*c0);
                *(float2*)&C[(size_t)(r+8)*NCH + c] =
                    make_float2(a1*c1 - b1*s1, a1*s1 + b1*c1);
            }
        } else {
            #pragma unroll
            for (int j = 0; j < 4; ++j) {
                const int c = n0 + wn*32 + j*8 + 2*q;
                *(float2*)&C[(size_t)(moff + r)*NCH + c] =
                    make_float2(acc[i][j][0], acc[i][j][1]);
                *(float2*)&C[(size_t)(moff + r + 8)*NCH + c] =
                    make_float2(acc[i][j][2], acc[i][j][3]);
            }
        }
    }
}

// ---------------- RNA tf32 pre-rounding ----------------------------------
__global__ void __launch_bounds__(256) round_tf32_k(
    const float4* __restrict__ in, float4* __restrict__ out, int n4)
{
    int i = blockIdx.x*256 + threadIdx.x;
    if (i < n4) {
        float4 v = in[i];
        v.x = to_tf32(v.x); v.y = to_tf32(v.y);
        v.z = to_tf32(v.z); v.w = to_tf32(v.w);
        out[i] = v;
    }
}

// ---------------- attention core ------------------------------------------
__global__ void __launch_bounds__(256) attn_kernel(
    const float* __restrict__ Kh, const float* __restrict__ Vh,
    const float* __restrict__ LQ, float* __restrict__ Part)
{
    __shared__ float qt[4096];
    __shared__ float KV[4096];
    __shared__ float Ss[4096];

    const int tid  = threadIdx.x;
    const int bh   = blockIdx.y;
    const int b    = bh >> 4, h = bh & 15;
    const int gx   = blockIdx.x;
    const int lt   = tid >> 4, ct = tid & 15;
    const int lane = tid & 31, warp = tid >> 5;

    #pragma unroll
    for (int it = 0; it < 16; ++it) {
        int e = tid + it*256;
        int d = e & 63, l = e >> 6;
        float v = LQ[(size_t)(l*NH + h)*ND + d];
        qt[d*64 + ((((l>>2) ^ (d & 15)) << 2) | (l & 3))] = v;
    }

    float att[4][4];
    #pragma unroll
    for (int i=0;i<4;i++)
        #pragma unroll
        for (int j=0;j<4;j++) att[i][j]=0.f;

    float4* KVv = (float4*)KV;
    const float4* qtv = (const float4*)qt;
    __syncthreads();

    for (int nn = 0; nn < 4; ++nn) {
        const int n = gx*4 + nn;
        const size_t rowbase = ((size_t)(b*NCHK + n)*64)*NCH + (size_t)h*ND;

        #pragma unroll
        for (int it = 0; it < 16; ++it) {
            int e = tid + it*256;
            int d = e & 63, c = e >> 6;
            KV[d*64 + ((((c>>2) ^ (d & 15)) << 2) | (c & 3))] =
                Kh[rowbase + (size_t)c*NCH + d];
        }
        __syncthreads();

        float s[4][4];
        #pragma unroll
        for (int i=0;i<4;i++)
            #pragma unroll
            for (int j=0;j<4;j++) s[i][j]=0.f;
        #pragma unroll 8
        for (int d = 0; d < 64; ++d) {
            float4 qv = qtv[d*16 + (lt ^ (d & 15))];
            float4 kv = KVv[d*16 + (ct ^ (d & 15))];
            s[0][0]+=qv.x*kv.x; s[0][1]+=qv.x*kv.y; s[0][2]+=qv.x*kv.z; s[0][3]+=qv.x*kv.w;
            s[1][0]+=qv.y*kv.x; s[1][1]+=qv.y*kv.y; s[1][2]+=qv.y*kv.z; s[1][3]+=qv.y*kv.w;
            s[2][0]+=qv.z*kv.x; s[2][1]+=qv.z*kv.y; s[2][2]+=qv.z*kv.z; s[2][3]+=qv.z*kv.w;
            s[3][0]+=qv.w*kv.x; s[3][1]+=qv.w*kv.y; s[3][2]+=qv.w*kv.z; s[3][3]+=qv.w*kv.w;
        }
        #pragma unroll
        for (int i=0;i<4;i++) {
            float4 o = make_float4(s[i][0]*0.125f, s[i][1]*0.125f,
                                   s[i][2]*0.125f, s[i][3]*0.125f);
            *(float4*)&Ss[(lt*4+i)*64 + ct*4] = o;
        }
        __syncthreads();

        #pragma unroll
        for (int it = 0; it < 16; ++it) {
            int e = tid + it*256;
            int d = e & 63, c = e >> 6;
            KV[c*64 + d] = Vh[rowbase + (size_t)c*NCH + d];
        }

        #pragma unroll
        for (int rr = 0; rr < 8; ++rr) {
            const int l = warp*8 + rr;
            float v0 = Ss[l*64 + lane];
            float v1 = Ss[l*64 + 32 + lane];
            const bool m0 = (lane <= l);
            const bool m1 = (32 + lane <= l);
            float mx = fmaxf(m0 ? v0 : -1e30f, m1 ? v1 : -1e30f);
            #pragma unroll
            for (int o = 16; o; o >>= 1) mx = fmaxf(mx, __shfl_xor_sync(~0u, mx, o));
            float e0 = m0 ? expf(v0 - mx) : 0.f;
            float e1 = m1 ? expf(v1 - mx) : 0.f;
            float sm = e0 + e1;
            #pragma unroll
            for (int o = 16; o; o >>= 1) sm += __shfl_xor_sync(~0u, sm, o);
            float r = 1.0f / sm;
            Ss[l*64 + lane]      = e0*r;
            Ss[l*64 + 32 + lane] = e1*r;
        }
        __syncthreads();

        #pragma unroll 8
        for (int c = 0; c < 64; ++c) {
            float4 vv = KVv[c*16 + ct];
            float p0 = Ss[(lt*4+0)*64 + c];
            float p1 = Ss[(lt*4+1)*64 + c];
            float p2 = Ss[(lt*4+2)*64 + c];
            float p3 = Ss[(lt*4+3)*64 + c];
            att[0][0]+=p0*vv.x; att[0][1]+=p0*vv.y; att[0][2]+=p0*vv.z; att[0][3]+=p0*vv.w;
            att[1][0]+=p1*vv.x; att[1][1]+=p1*vv.y; att[1][2]+=p1*vv.z; att[1][3]+=p1*vv.w;
            att[2][0]+=p2*vv.x; att[2][1]+=p2*vv.y; att[2][2]+=p2*vv.z; att[2][3]+=p2*vv.w;
            att[3][0]+=p3*vv.x; att[3][1]+=p3*vv.y; att[3][2]+=p3*vv.z; att[3][3]+=p3*vv.w;
        }
        __syncthreads();
    }

    const size_t obase = ((size_t)(gx*128 + bh))*4096;
    #pragma unroll
    for (int i = 0; i < 4; ++i) {
        float4 o = make_float4(att[i][0], att[i][1], att[i][2], att[i][3]);
        *(float4*)&Part[obase + (lt*4+i)*64 + ct*4] = o;
    }
}

// ---------------- U kernel (fused partial reduce):
// Ut[b][c][h*64+l] = sum_d (sum_g Part[g][bh][l][d]) * Wp[c][h*64+d]
__global__ void __launch_bounds__(256) u_kernel(
    const float* __restrict__ Part, const float* __restrict__ Wp,
    float* __restrict__ Ut)
{
    extern __shared__ float us[];          // As 64x68 | Ws 128x68 (floats)
    float4* As4 = (float4*)us;             // stride 17 float4
    float4* Ws4 = (float4*)(us + 64*68);   // stride 17 float4

    const int tid  = threadIdx.x;
    const int cblk = blockIdx.x;
    const int bh   = blockIdx.y;
    const int b    = bh >> 4, h = bh & 15;

    const float4* Pf = (const float4*)Part;
    #pragma unroll
    for (int it = 0; it < 4; ++it) {
        int e = tid + it*256;              // 1024 float4 per bh
        int l = e >> 4, d4 = e & 15;
        float4 s = make_float4(0.f, 0.f, 0.f, 0.f);
        #pragma unroll
        for (int gp = 0; gp < 8; ++gp) {
            float4 v = Pf[(size_t)(gp*128 + bh)*1024 + e];
            s.x += v.x; s.y += v.y; s.z += v.z; s.w += v.w;
        }
        As4[l*17 + d4] = s;
    }
    const float4* Wf = (const float4*)Wp;
    #pragma unroll
    for (int it = 0; it < 8; ++it) {
        int e = tid + it*256;              // 2048 float4
        int cl = e >> 4, d4 = e & 15;
        Ws4[cl*17 + d4] = Wf[(size_t)(cblk*128 + cl)*256 + h*16 + d4];
    }
    __syncthreads();

    const int cg = tid >> 4;               // 0..15 (8 c each)
    const int lg = tid & 15;               // 0..15 (4 l each)
    float acc[8][4];
    #pragma unroll
    for (int i = 0; i < 8; ++i)
        #pragma unroll
        for (int j = 0; j < 4; ++j) acc[i][j] = 0.f;

    #pragma unroll 4
    for (int d4 = 0; d4 < 16; ++d4) {
        float4 a[4], w[8];
        #pragma unroll
        for (int j = 0; j < 4; ++j) a[j] = As4[(lg*4 + j)*17 + d4];
        #pragma unroll
        for (int i = 0; i < 8; ++i) w[i] = Ws4[(cg*8 + i)*17 + d4];
        #pragma unroll
        for (int i = 0; i < 8; ++i)
            #pragma unroll
            for (int j = 0; j < 4; ++j)
                acc[i][j] += w[i].x*a[j].x + w[i].y*a[j].y
                           + w[i].z*a[j].z + w[i].w*a[j].w;
    }

    #pragma unroll
    for (int i = 0; i < 8; ++i) {
        const int c = cblk*128 + cg*8 + i;
        #pragma unroll
        for (int j = 0; j < 4; ++j) {
            const int l = lg*4 + j;
            Ut[(size_t)b*1048576 + (size_t)c*1024 + h*64 + l] = to_tf32(acc[i][j]);
        }
    }
}

// ---------------- launch ---------------------------------------------------
extern "C" void kernel_launch(void* const* d_in, const int* in_sizes, int n_in,
                              void* d_out, int out_size)
{
    const float* x   = (const float*)d_in[0];
    const float* lq  = (const float*)d_in[1];
    const float* W_k = (const float*)d_in[2];
    const float* W_v = (const float*)d_in[3];
    const float* W_g = (const float*)d_in[4];
    const float* W_p = (const float*)d_in[5];
    float* out = (float*)d_out;

    float *Kh, *Vh, *G, *Ut, *xr, *Wr, *Part;
    cudaGetSymbolAddress((void**)&Kh,   g_Kh);
    cudaGetSymbolAddress((void**)&Vh,   g_Vh);
    cudaGetSymbolAddress((void**)&G,    g_G);
    cudaGetSymbolAddress((void**)&Ut,   g_Ut);
    cudaGetSymbolAddress((void**)&xr,   g_xr);
    cudaGetSymbolAddress((void**)&Wr,   g_Wr);
    cudaGetSymbolAddress((void**)&Part, g_attn_part);

    const int SMEM = 3 * STG;   // 96 KB -> 2 CTAs/SM
    cudaFuncSetAttribute(gemm_tc<1>, cudaFuncAttributeMaxDynamicSharedMemorySize, SMEM);
    cudaFuncSetAttribute(gemm_tc<2>, cudaFuncAttributeMaxDynamicSharedMemorySize, SMEM);
    cudaFuncSetAttribute(gemm_tc<3>, cudaFuncAttributeMaxDynamicSharedMemorySize, SMEM);
    cudaFuncSetAttribute(gemm_tc<4>, cudaFuncAttributeMaxDynamicSharedMemorySize, SMEM);
    const int USMEM = (64*68 + 128*68) * 4;   // 52224 B
    cudaFuncSetAttribute(u_kernel, cudaFuncAttributeMaxDynamicSharedMemorySize, USMEM);

    // rounding
    round_tf32_k<<<32768, 256>>>((const float4*)x,   (float4*)xr,               8388608);
    round_tf32_k<<<1024, 256>>>((const float4*)W_g, (float4*)(Wr + 2*1048576), 262144);
    round_tf32_k<<<1024, 256>>>((const float4*)W_k, (float4*)(Wr + 0*1048576), 262144);
    round_tf32_k<<<1024, 256>>>((const float4*)W_v, (float4*)(Wr + 1*1048576), 262144);

    // GEMMs
    gemm_tc<4><<<dim3(8, 256), 256, SMEM>>>(xr, Wr + 2*1048576, G);   // gates (fused softmax)
    gemm_tc<2><<<dim3(8, 128), 256, SMEM>>>(xr, Wr + 0*1048576, Kh);  // K + rope
    gemm_tc<1><<<dim3(8, 128), 256, SMEM>>>(xr, Wr + 1*1048576, Vh);  // V

    // attention path
    attn_kernel<<<dim3(8, 128), 256>>>(Kh, Vh, lq, Part);
    u_kernel   <<<dim3(8, 128), 256, USMEM>>>(Part, W_p, Ut);

    // out[b*4096+t][c] = sum_{hl} gates[row][hl] * Ut[b][c][hl]
    gemm_tc<3><<<dim3(8, 32, 8), 256, SMEM>>>(G, Ut, out);
}